// round 1
// baseline (speedup 1.0000x reference)
#include <cuda_runtime.h>
#include <math.h>

// Problem constants
#define PS   16      // slots
#define PB   8       // batch
#define PL   8       // steps
#define PV   32000   // vocab
#define PD   1024    // hidden
#define PT   512     // time
#define PG   3       // gates
#define SLB  1024    // PS*PL*PB
#define D3   3072    // 3*PD
#define OUT_PTR_ELEMS 32768000LL  // S*B*L*V

// ---------------- device scratch (allocation-free) ----------------
__device__ float g_x[SLB * PD];        // decoder inputs  (m = (s*L+l)*B+b)
__device__ float g_h[SLB * PD];        // GRU hidden
__device__ float g_gi[SLB * D3];       // x @ w_ih^T
__device__ float g_gh[PB * D3];        // h0 @ w_hh^T + b_hh
__device__ float g_scores[SLB * PT];   // layout: slrow*4096 + b*512 + t
__device__ float g_probs[SLB * PT];    // layout: m*512 + t
__device__ float g_ctx[SLB * PD];      // context
__device__ float g_pgen[SLB];

// ---------------- reductions ----------------
__device__ __forceinline__ float warpMax(float v) {
    #pragma unroll
    for (int o = 16; o; o >>= 1) v = fmaxf(v, __shfl_xor_sync(0xffffffffu, v, o));
    return v;
}
__device__ __forceinline__ float warpSum(float v) {
    #pragma unroll
    for (int o = 16; o; o >>= 1) v += __shfl_xor_sync(0xffffffffu, v, o);
    return v;
}
__device__ float blockMax(float v) {
    __shared__ float sm[32];
    v = warpMax(v);
    int w = threadIdx.x >> 5, l = threadIdx.x & 31;
    __syncthreads();
    if (l == 0) sm[w] = v;
    __syncthreads();
    int nw = (blockDim.x + 31) >> 5;
    v = (threadIdx.x < nw) ? sm[threadIdx.x] : -INFINITY;
    if (w == 0) v = warpMax(v);
    if (threadIdx.x == 0) sm[0] = v;
    __syncthreads();
    return sm[0];
}
__device__ float blockSum(float v) {
    __shared__ float sm[32];
    v = warpSum(v);
    int w = threadIdx.x >> 5, l = threadIdx.x & 31;
    __syncthreads();
    if (l == 0) sm[w] = v;
    __syncthreads();
    int nw = (blockDim.x + 31) >> 5;
    v = (threadIdx.x < nw) ? sm[threadIdx.x] : 0.0f;
    if (w == 0) v = warpSum(v);
    if (threadIdx.x == 0) sm[0] = v;
    __syncthreads();
    return sm[0];
}

// ---------------- generic 128x128x8 tiled SGEMM ----------------
// C = A @ op(B).   A: rows x K row-major (lda element stride, + z*a_batch)
// TRANSB=true : B is (N x K) row-major -> dot(A_row, B_row)
// TRANSB=false: B is (K x N) row-major
// PERMUTE=true: C row offset = ((s*B+b)*L+l)*V, with m = s*64+l*8+b (logits epilogue)
// else        : C[z*c_batch + m*ldc + n]
// Requires M%128==0, N%128==0, K%8==0, blockDim=256.
template <bool TRANSB, bool PERMUTE>
__global__ void gemm128(const float* __restrict__ A, int lda, long long a_batch,
                        const float* __restrict__ B, int ldb, long long b_batch,
                        float* __restrict__ C, int ldc, long long c_batch,
                        int K)
{
    __shared__ float As[8][128];
    __shared__ float Bs[8][128];

    const int z = blockIdx.z;
    const float* Ab = A + (long long)z * a_batch;
    const float* Bb = B + (long long)z * b_batch;
    const int m0 = blockIdx.y * 128;
    const int n0 = blockIdx.x * 128;

    const int tid = threadIdx.x;
    const int tx = tid & 15;   // col group
    const int ty = tid >> 4;   // row group

    float acc[8][8];
    #pragma unroll
    for (int i = 0; i < 8; i++)
        #pragma unroll
        for (int j = 0; j < 8; j++) acc[i][j] = 0.0f;

    const int arow = tid >> 1;        // 0..127
    const int acol = (tid & 1) * 4;   // 0 or 4
    const int krow = tid >> 5;        // 0..7   (NN B load)
    const int ncol = (tid & 31) * 4;  // 0..124 (NN B load)

    for (int k0 = 0; k0 < K; k0 += 8) {
        // A tile (transposed into smem)
        float4 av = *reinterpret_cast<const float4*>(
            &Ab[(long long)(m0 + arow) * lda + k0 + acol]);
        As[acol + 0][arow] = av.x;
        As[acol + 1][arow] = av.y;
        As[acol + 2][arow] = av.z;
        As[acol + 3][arow] = av.w;

        if (TRANSB) {
            float4 bv = *reinterpret_cast<const float4*>(
                &Bb[(long long)(n0 + arow) * ldb + k0 + acol]);
            Bs[acol + 0][arow] = bv.x;
            Bs[acol + 1][arow] = bv.y;
            Bs[acol + 2][arow] = bv.z;
            Bs[acol + 3][arow] = bv.w;
        } else {
            float4 bv = *reinterpret_cast<const float4*>(
                &Bb[(long long)(k0 + krow) * ldb + n0 + ncol]);
            *reinterpret_cast<float4*>(&Bs[krow][ncol]) = bv;
        }
        __syncthreads();

        #pragma unroll
        for (int kk = 0; kk < 8; kk++) {
            float ar[8], br[8];
            *reinterpret_cast<float4*>(&ar[0]) = *reinterpret_cast<float4*>(&As[kk][ty * 8]);
            *reinterpret_cast<float4*>(&ar[4]) = *reinterpret_cast<float4*>(&As[kk][ty * 8 + 4]);
            *reinterpret_cast<float4*>(&br[0]) = *reinterpret_cast<float4*>(&Bs[kk][tx * 8]);
            *reinterpret_cast<float4*>(&br[4]) = *reinterpret_cast<float4*>(&Bs[kk][tx * 8 + 4]);
            #pragma unroll
            for (int i = 0; i < 8; i++)
                #pragma unroll
                for (int j = 0; j < 8; j++)
                    acc[i][j] = fmaf(ar[i], br[j], acc[i][j]);
        }
        __syncthreads();
    }

    #pragma unroll
    for (int i = 0; i < 8; i++) {
        const int m = m0 + ty * 8 + i;
        long long rowoff;
        if (PERMUTE) {
            // m = s*64 + l*8 + b  ->  out row ((s*B+b)*L+l)
            int s = m >> 6, l = (m >> 3) & 7, b = m & 7;
            rowoff = (long long)((s * 8 + b) * 8 + l) * (long long)PV;
        } else {
            rowoff = (long long)z * c_batch + (long long)m * ldc;
        }
        #pragma unroll
        for (int j = 0; j < 8; j += 4) {
            float4 v = make_float4(acc[i][j], acc[i][j + 1], acc[i][j + 2], acc[i][j + 3]);
            *reinterpret_cast<float4*>(&C[rowoff + n0 + tx * 8 + j]) = v;
        }
    }
}

// ---------------- small kernels ----------------

// gh[b,e] = b_hh[e] + dot(h0[b,:], w_hh[e,:])
__global__ void gh_kernel(const float* __restrict__ h0, const float* __restrict__ whh,
                          const float* __restrict__ bhh)
{
    int i = blockIdx.x * 256 + threadIdx.x;
    if (i >= PB * D3) return;
    int b = i / D3, e = i % D3;
    float acc = bhh[e];
    const float4* hr = reinterpret_cast<const float4*>(h0 + b * PD);
    const float4* wr = reinterpret_cast<const float4*>(whh + (long long)e * PD);
    #pragma unroll 4
    for (int k = 0; k < PD / 4; k++) {
        float4 a = hr[k], w = wr[k];
        acc = fmaf(a.x, w.x, acc); acc = fmaf(a.y, w.y, acc);
        acc = fmaf(a.z, w.z, acc); acc = fmaf(a.w, w.w, acc);
    }
    g_gh[i] = acc;
}

// x[m,d]: l==0 -> slot_emb[s], else embedding[trg[b,s,l-1]]
__global__ void build_x(const float* __restrict__ emb, const float* __restrict__ slot,
                        const int* __restrict__ trg)
{
    int idx = blockIdx.x * 256 + threadIdx.x;   // SLB*PD total
    int d = idx & (PD - 1);
    int m = idx >> 10;
    int s = m >> 6, l = (m >> 3) & 7, b = m & 7;
    float v;
    if (l == 0) {
        v = slot[s * PD + d];
    } else {
        int tok = trg[b * (PS * PL) + s * PL + (l - 1)];
        v = emb[(long long)tok * PD + d];
    }
    g_x[idx] = v;
}

// GRU combine: h = (1-z)*n + z*h0
__global__ void gru_kernel(const float* __restrict__ bih, const float* __restrict__ h0)
{
    int idx = blockIdx.x * 256 + threadIdx.x;   // SLB*PD
    int d = idx & (PD - 1);
    int m = idx >> 10;
    int b = m & 7;
    long long gb = (long long)m * D3;
    float ir = g_gi[gb + d]          + bih[d];
    float iz = g_gi[gb + PD + d]     + bih[PD + d];
    float in = g_gi[gb + 2 * PD + d] + bih[2 * PD + d];
    float hr = g_gh[b * D3 + d];
    float hz = g_gh[b * D3 + PD + d];
    float hn = g_gh[b * D3 + 2 * PD + d];
    float r = 1.0f / (1.0f + expf(-(ir + hr)));
    float z = 1.0f / (1.0f + expf(-(iz + hz)));
    float n = tanhf(in + r * hn);
    g_h[idx] = (1.0f - z) * n + z * h0[b * PD + d];
}

// softmax over T for probs (blocks = SLB, threads = 256)
__global__ void probs_kernel()
{
    int m = blockIdx.x;
    long long base = (long long)(m >> 3) * (PB * PT) + (long long)(m & 7) * PT;
    int t = threadIdx.x;
    float v0 = g_scores[base + t];
    float v1 = g_scores[base + t + 256];
    float mx = blockMax(fmaxf(v0, v1));
    float e0 = expf(v0 - mx), e1 = expf(v1 - mx);
    float sum = blockSum(e0 + e1);
    float inv = 1.0f / sum;
    g_probs[m * PT + t] = e0 * inv;
    g_probs[m * PT + t + 256] = e1 * inv;
}

// p_gen = sigmoid(dot([h,ctx,x], w_ratio) + b)   (blocks = SLB, threads = 256)
__global__ void pgen_kernel(const float* __restrict__ w, const float* __restrict__ wb)
{
    int m = blockIdx.x;
    long long base = (long long)m * PD;
    float p = 0.0f;
    for (int d = threadIdx.x; d < PD; d += 256) {
        p = fmaf(g_h[base + d],   w[d],          p);
        p = fmaf(g_ctx[base + d], w[PD + d],     p);
        p = fmaf(g_x[base + d],   w[2 * PD + d], p);
    }
    p = blockSum(p);
    if (threadIdx.x == 0)
        g_pgen[m] = 1.0f / (1.0f + expf(-(p + wb[0])));
}

// row softmax over V in-place on out, scaled by p_gen (blocks = SLB out-rows)
__global__ void softmax_v(float* __restrict__ out)
{
    int o = blockIdx.x;  // out row index: (s*B+b)*L + l
    long long base = (long long)o * PV;
    int s = o >> 6, b = (o >> 3) & 7, l = o & 7;
    int m = s * 64 + l * 8 + b;
    float pg = g_pgen[m];

    float mx = -INFINITY;
    for (int i = threadIdx.x; i < PV; i += 256) mx = fmaxf(mx, out[base + i]);
    mx = blockMax(mx);

    float sum = 0.0f;
    for (int i = threadIdx.x; i < PV; i += 256) {
        float e = expf(out[base + i] - mx);
        out[base + i] = e;
        sum += e;
    }
    sum = blockSum(sum);
    float sc = pg / sum;
    for (int i = threadIdx.x; i < PV; i += 256) out[base + i] *= sc;
}

// scatter-add copy distribution (blocks = SLB, threads = T)
__global__ void scatter_kernel(float* __restrict__ out, const int* __restrict__ story)
{
    int m = blockIdx.x;
    int t = threadIdx.x;
    int s = m >> 6, l = (m >> 3) & 7, b = m & 7;
    long long obase = (long long)((s * 8 + b) * 8 + l) * (long long)PV;
    float w = 1.0f - g_pgen[m];
    int tok = story[b * PT + t];
    atomicAdd(&out[obase + tok], w * g_probs[m * PT + t]);
}

// gate_outputs[s,b,g] = ctx[s, l=0, b, :] . w_gate[g] + b  (blocks = S*B*G, threads=128)
__global__ void gate_kernel(float* __restrict__ out, const float* __restrict__ wg,
                            const float* __restrict__ bg)
{
    int o = blockIdx.x;              // (s*B+b)*G + g
    int s = o / (PB * PG);
    int b = (o % (PB * PG)) / PG;
    int g = o % PG;
    int m = s * 64 + b;              // l = 0
    float p = 0.0f;
    for (int d = threadIdx.x; d < PD; d += 128)
        p = fmaf(g_ctx[(long long)m * PD + d], wg[g * PD + d], p);
    p = blockSum(p);
    if (threadIdx.x == 0) out[OUT_PTR_ELEMS + o] = p + bg[g];
}

// ---------------- launch ----------------
extern "C" void kernel_launch(void* const* d_in, const int* in_sizes, int n_in,
                              void* d_out, int out_size)
{
    const float* enc_h   = (const float*)d_in[0];   // (B,D)
    const float* enc_out = (const float*)d_in[1];   // (B,T,D)
    const int*   story   = (const int*)d_in[2];     // (B,T)
    const int*   trg     = (const int*)d_in[3];     // (B,S,L)
    const float* emb     = (const float*)d_in[4];   // (V,D)
    const float* w_ih    = (const float*)d_in[5];   // (3D,D)
    const float* w_hh    = (const float*)d_in[6];   // (3D,D)
    const float* b_ih    = (const float*)d_in[7];
    const float* b_hh    = (const float*)d_in[8];
    const float* w_rw    = (const float*)d_in[9];   // (1,3D)
    const float* w_rb    = (const float*)d_in[10];
    const float* w_gw    = (const float*)d_in[11];  // (G,D)
    const float* w_gb    = (const float*)d_in[12];
    const float* slot    = (const float*)d_in[13];  // (S,D)
    float* out = (float*)d_out;

    float *px, *ph, *pgi, *psc, *pcx;
    cudaGetSymbolAddress((void**)&px,  g_x);
    cudaGetSymbolAddress((void**)&ph,  g_h);
    cudaGetSymbolAddress((void**)&pgi, g_gi);
    cudaGetSymbolAddress((void**)&psc, g_scores);
    cudaGetSymbolAddress((void**)&pcx, g_ctx);

    // 1) decoder inputs x
    build_x<<<(SLB * PD) / 256, 256>>>(emb, slot, trg);

    // 2) gh = h0 @ w_hh^T + b_hh
    gh_kernel<<<(PB * D3 + 255) / 256, 256>>>(enc_h, w_hh, b_hh);

    // 3) gi = x @ w_ih^T   (M=1024, N=3072, K=1024)
    gemm128<true, false><<<dim3(D3 / 128, SLB / 128, 1), 256>>>(
        px, PD, 0, w_ih, PD, 0, pgi, D3, 0, PD);

    // 4) GRU combine -> h
    gru_kernel<<<(SLB * PD) / 256, 256>>>(b_ih, enc_h);

    // 5) scores[slrow,b,t] = h . enc_out[b,t]   (per-b: M=128, N=512, K=1024)
    gemm128<true, false><<<dim3(PT / 128, (PS * PL) / 128, PB), 256>>>(
        ph, PB * PD, PD, enc_out, PD, (long long)PT * PD,
        psc, PB * PT, PT, PD);

    // 6) probs = softmax_t(scores)
    probs_kernel<<<SLB, 256>>>();

    // 7) context = scores @ enc_out[b]   (per-b: M=128, N=1024, K=512)
    gemm128<false, false><<<dim3(PD / 128, (PS * PL) / 128, PB), 256>>>(
        psc, PB * PT, PT, enc_out, PD, (long long)PT * PD,
        pcx, PB * PD, PD, PT);

    // 8) p_gen
    pgen_kernel<<<SLB, 256>>>(w_rw, w_rb);

    // 9) logits = h @ E^T, written permuted into out  (M=1024, N=32000, K=1024)
    gemm128<true, true><<<dim3(PV / 128, SLB / 128, 1), 256>>>(
        ph, PD, 0, emb, PD, 0, out, 0, 0, PD);

    // 10) out = p_gen * softmax_v(logits)
    softmax_v<<<SLB, 256>>>(out);

    // 11) out += (1-p_gen) * scatter(probs)
    scatter_kernel<<<SLB, PT>>>(out, story);

    // 12) gate outputs
    gate_kernel<<<PS * PB * PG, 128>>>(out, w_gw, w_gb);
}

// round 3
// speedup vs baseline: 1.8542x; 1.8542x over previous
#include <cuda_runtime.h>
#include <cuda_bf16.h>
#include <math.h>
#include <stdint.h>

// Problem constants
#define PS   16
#define PB   8
#define PL   8
#define PV   32000
#define PD   1024
#define PT   512
#define PG   3
#define SLB  1024
#define D3   3072
#define OUT_PTR_ELEMS 32768000LL

// ---------------- device scratch ----------------
__device__ float g_x[SLB * PD];
__device__ float g_h[SLB * PD];
__device__ float g_gi[SLB * D3];
__device__ float g_gh[PB * D3];
__device__ float g_scores[SLB * PT];
__device__ float g_probs[SLB * PT];
__device__ float g_ctx[SLB * PD];
__device__ float g_pgen[SLB];
// split-precision bf16 operands: row-major, pitch 2048 (cols [0,1024)=hi, [1024,2048)=lo)
__device__ __nv_bfloat16 g_B2[(long long)PV * 2048];
__device__ __nv_bfloat16 g_A2h[SLB * 2048];
__device__ __nv_bfloat16 g_A2x[SLB * 2048];
__device__ __nv_bfloat16 g_W2[D3 * 2048];

// ---------------- helpers ----------------
__device__ __forceinline__ uint32_t smem_u32(const void* p) {
    uint32_t a;
    asm("{ .reg .u64 t; cvta.to.shared.u64 t, %1; cvt.u32.u64 %0, t; }" : "=r"(a) : "l"(p));
    return a;
}
__device__ __forceinline__ void cp16(uint32_t s, const void* g) {
    asm volatile("cp.async.cg.shared.global [%0], [%1], 16;" :: "r"(s), "l"(g) : "memory");
}
__device__ __forceinline__ void cp_commit() {
    asm volatile("cp.async.commit_group;" ::: "memory");
}
template <int N>
__device__ __forceinline__ void cp_wait() {
    asm volatile("cp.async.wait_group %0;" :: "n"(N) : "memory");
}
__device__ __forceinline__ void mma16816(float& c0, float& c1, float& c2, float& c3,
                                         uint32_t a0, uint32_t a1, uint32_t a2, uint32_t a3,
                                         uint32_t b0, uint32_t b1) {
    asm volatile("mma.sync.aligned.m16n8k16.row.col.f32.bf16.bf16.f32 "
                 "{%0,%1,%2,%3}, {%4,%5,%6,%7}, {%8,%9}, {%0,%1,%2,%3};"
                 : "+f"(c0), "+f"(c1), "+f"(c2), "+f"(c3)
                 : "r"(a0), "r"(a1), "r"(a2), "r"(a3), "r"(b0), "r"(b1));
}
// swizzled byte offset within a 128row x 64B tile
__device__ __forceinline__ uint32_t swz(int r, int kb) {
    return (uint32_t)(r * 64 + ((((kb >> 4) ^ ((r >> 1) & 3)) << 4) | (kb & 15)));
}

// ---------------- reductions ----------------
__device__ __forceinline__ float warpMax(float v) {
    #pragma unroll
    for (int o = 16; o; o >>= 1) v = fmaxf(v, __shfl_xor_sync(0xffffffffu, v, o));
    return v;
}
__device__ __forceinline__ float warpSum(float v) {
    #pragma unroll
    for (int o = 16; o; o >>= 1) v += __shfl_xor_sync(0xffffffffu, v, o);
    return v;
}
__device__ float blockSum(float v) {
    __shared__ float sm[32];
    v = warpSum(v);
    int w = threadIdx.x >> 5, l = threadIdx.x & 31;
    __syncthreads();
    if (l == 0) sm[w] = v;
    __syncthreads();
    int nw = (blockDim.x + 31) >> 5;
    v = (threadIdx.x < nw) ? sm[threadIdx.x] : 0.0f;
    if (w == 0) v = warpSum(v);
    if (threadIdx.x == 0) sm[0] = v;
    __syncthreads();
    return sm[0];
}
__device__ float blockMax(float v) {
    __shared__ float sm[32];
    v = warpMax(v);
    int w = threadIdx.x >> 5, l = threadIdx.x & 31;
    __syncthreads();
    if (l == 0) sm[w] = v;
    __syncthreads();
    int nw = (blockDim.x + 31) >> 5;
    v = (threadIdx.x < nw) ? sm[threadIdx.x] : -INFINITY;
    if (w == 0) v = warpMax(v);
    if (threadIdx.x == 0) sm[0] = v;
    __syncthreads();
    return sm[0];
}

// ---------------- split-precision conversion ----------------
__global__ void split_kernel(const float* __restrict__ src, __nv_bfloat16* __restrict__ dst, int nrow)
{
    long long idx = (long long)blockIdx.x * 256 + threadIdx.x;
    long long tot = (long long)nrow * 256;
    if (idx >= tot) return;
    long long row = idx >> 8;
    int c4 = (int)(idx & 255);
    float4 v = reinterpret_cast<const float4*>(src + row * 1024)[c4];
    __nv_bfloat162 h0 = __floats2bfloat162_rn(v.x, v.y);
    __nv_bfloat162 h1 = __floats2bfloat162_rn(v.z, v.w);
    float2 f0 = __bfloat1622float2(h0);
    float2 f1 = __bfloat1622float2(h1);
    __nv_bfloat162 l0 = __floats2bfloat162_rn(v.x - f0.x, v.y - f0.y);
    __nv_bfloat162 l1 = __floats2bfloat162_rn(v.z - f1.x, v.w - f1.y);
    __nv_bfloat162* dh = reinterpret_cast<__nv_bfloat162*>(dst + row * 2048 + c4 * 4);
    dh[0] = h0; dh[1] = h1;
    __nv_bfloat162* dl = reinterpret_cast<__nv_bfloat162*>(dst + row * 2048 + 1024 + c4 * 4);
    dl[0] = l0; dl[1] = l1;
}

// ---------------- HMMA split-precision GEMM ----------------
// C[m,n] = sum_seg A2[m, aseg:aseg+1024] . B2[n, bseg:bseg+1024]
// segments: (hi,hi), (hi,lo), (lo,hi).
// CTA tile 128x128, 8 warps (2m x 4n), warp tile 64x32, k-chunk 32, 4-stage cp.async.
#define STAGES 4
#define CHUNKS 96
#define MMA_SMEM (STAGES * 16384)

template <bool PERMUTE>
__global__ void __launch_bounds__(256, 1) mma_gemm(
    const __nv_bfloat16* __restrict__ A2,
    const __nv_bfloat16* __restrict__ B2,
    float* __restrict__ C, long long ldc)
{
    extern __shared__ char smd[];
    const uint32_t sbase = smem_u32(smd);
    const int tid = threadIdx.x;
    const int wid = tid >> 5;
    const int lane = tid & 31;
    const int lr = lane >> 2;        // 0..7
    const int q4 = (lane & 3) * 4;   // byte offset of k pair
    const int mr = (wid & 1) * 64;
    const int nc = (wid >> 1) * 32;
    const long long m0 = (long long)blockIdx.y * 128;
    const long long n0 = (long long)blockIdx.x * 128;

    // cp.async source/dst indices for this thread (2 rows per operand)
    const int r_a = tid >> 2;          // 0..63  (i=0), +64 (i=1)
    const int g_a = tid & 3;

    float acc[4][4][4];
    #pragma unroll
    for (int i = 0; i < 4; i++)
        #pragma unroll
        for (int j = 0; j < 4; j++)
            #pragma unroll
            for (int k = 0; k < 4; k++) acc[i][j][k] = 0.0f;

    const int ASEG[3] = {0, 0, 1024};
    const int BSEG[3] = {0, 1024, 0};

    auto issue = [&](int c) {
        const int seg = c >> 5;
        const int off = (c & 31) << 5;
        const int acol = ASEG[seg] + off;
        const int bcol = BSEG[seg] + off;
        const uint32_t Ab = sbase + (uint32_t)((c & (STAGES - 1)) * 16384);
        const uint32_t Bb = Ab + 8192;
        #pragma unroll
        for (int i = 0; i < 2; i++) {
            const int r = r_a + i * 64;
            const uint32_t so = (uint32_t)(r * 64 + ((g_a ^ ((r >> 1) & 3)) << 4));
            cp16(Ab + so, A2 + (m0 + r) * 2048 + acol + g_a * 8);
            cp16(Bb + so, B2 + (n0 + r) * 2048 + bcol + g_a * 8);
        }
        cp_commit();
    };

    #pragma unroll
    for (int s = 0; s < STAGES - 1; s++) issue(s);

    #pragma unroll 1
    for (int c = 0; c < CHUNKS; c++) {
        cp_wait<STAGES - 2>();
        __syncthreads();
        if (c + STAGES - 1 < CHUNKS) issue(c + STAGES - 1);

        const char* Ab = smd + (c & (STAGES - 1)) * 16384;
        const char* Bb = Ab + 8192;

        #pragma unroll
        for (int kc2 = 0; kc2 < 2; kc2++) {
            const int kb0 = kc2 * 32 + q4;
            uint32_t a[4][4], b[4][2];
            #pragma unroll
            for (int fm = 0; fm < 4; fm++) {
                const int r = mr + fm * 16 + lr;
                a[fm][0] = *(const uint32_t*)(Ab + swz(r,     kb0));
                a[fm][1] = *(const uint32_t*)(Ab + swz(r + 8, kb0));
                a[fm][2] = *(const uint32_t*)(Ab + swz(r,     kb0 + 16));
                a[fm][3] = *(const uint32_t*)(Ab + swz(r + 8, kb0 + 16));
            }
            #pragma unroll
            for (int fn = 0; fn < 4; fn++) {
                const int n = nc + fn * 8 + lr;
                b[fn][0] = *(const uint32_t*)(Bb + swz(n, kb0));
                b[fn][1] = *(const uint32_t*)(Bb + swz(n, kb0 + 16));
            }
            #pragma unroll
            for (int fm = 0; fm < 4; fm++)
                #pragma unroll
                for (int fn = 0; fn < 4; fn++)
                    mma16816(acc[fm][fn][0], acc[fm][fn][1], acc[fm][fn][2], acc[fm][fn][3],
                             a[fm][0], a[fm][1], a[fm][2], a[fm][3], b[fn][0], b[fn][1]);
        }
    }

    // epilogue
    #pragma unroll
    for (int fm = 0; fm < 4; fm++) {
        const int mrow0 = (int)m0 + mr + fm * 16 + lr;
        const int mrow1 = mrow0 + 8;
        long long ro0, ro1;
        if (PERMUTE) {
            int s0 = mrow0 >> 6, l0 = (mrow0 >> 3) & 7, b0 = mrow0 & 7;
            int s1 = mrow1 >> 6, l1 = (mrow1 >> 3) & 7, b1 = mrow1 & 7;
            ro0 = (long long)((s0 * 8 + b0) * 8 + l0) * (long long)PV;
            ro1 = (long long)((s1 * 8 + b1) * 8 + l1) * (long long)PV;
        } else {
            ro0 = (long long)mrow0 * ldc;
            ro1 = (long long)mrow1 * ldc;
        }
        #pragma unroll
        for (int fn = 0; fn < 4; fn++) {
            const long long col = n0 + nc + fn * 8 + (lane & 3) * 2;
            *reinterpret_cast<float2*>(C + ro0 + col) = make_float2(acc[fm][fn][0], acc[fm][fn][1]);
            *reinterpret_cast<float2*>(C + ro1 + col) = make_float2(acc[fm][fn][2], acc[fm][fn][3]);
        }
    }
}

// ---------------- fp32 tiled SGEMM (scores/context) ----------------
template <bool TRANSB>
__global__ void gemm128(const float* __restrict__ A, int lda, long long a_batch,
                        const float* __restrict__ B, int ldb, long long b_batch,
                        float* __restrict__ C, int ldc, long long c_batch,
                        int K)
{
    __shared__ float As[8][128];
    __shared__ float Bs[8][128];
    const int z = blockIdx.z;
    const float* Ab = A + (long long)z * a_batch;
    const float* Bb = B + (long long)z * b_batch;
    const int m0 = blockIdx.y * 128;
    const int n0 = blockIdx.x * 128;
    const int tid = threadIdx.x;
    const int tx = tid & 15;
    const int ty = tid >> 4;
    float acc[8][8];
    #pragma unroll
    for (int i = 0; i < 8; i++)
        #pragma unroll
        for (int j = 0; j < 8; j++) acc[i][j] = 0.0f;
    const int arow = tid >> 1;
    const int acol = (tid & 1) * 4;
    const int krow = tid >> 5;
    const int ncol = (tid & 31) * 4;
    for (int k0 = 0; k0 < K; k0 += 8) {
        float4 av = *reinterpret_cast<const float4*>(&Ab[(long long)(m0 + arow) * lda + k0 + acol]);
        As[acol + 0][arow] = av.x; As[acol + 1][arow] = av.y;
        As[acol + 2][arow] = av.z; As[acol + 3][arow] = av.w;
        if (TRANSB) {
            float4 bv = *reinterpret_cast<const float4*>(&Bb[(long long)(n0 + arow) * ldb + k0 + acol]);
            Bs[acol + 0][arow] = bv.x; Bs[acol + 1][arow] = bv.y;
            Bs[acol + 2][arow] = bv.z; Bs[acol + 3][arow] = bv.w;
        } else {
            float4 bv = *reinterpret_cast<const float4*>(&Bb[(long long)(k0 + krow) * ldb + n0 + ncol]);
            *reinterpret_cast<float4*>(&Bs[krow][ncol]) = bv;
        }
        __syncthreads();
        #pragma unroll
        for (int kk = 0; kk < 8; kk++) {
            float ar[8], br[8];
            *reinterpret_cast<float4*>(&ar[0]) = *reinterpret_cast<float4*>(&As[kk][ty * 8]);
            *reinterpret_cast<float4*>(&ar[4]) = *reinterpret_cast<float4*>(&As[kk][ty * 8 + 4]);
            *reinterpret_cast<float4*>(&br[0]) = *reinterpret_cast<float4*>(&Bs[kk][tx * 8]);
            *reinterpret_cast<float4*>(&br[4]) = *reinterpret_cast<float4*>(&Bs[kk][tx * 8 + 4]);
            #pragma unroll
            for (int i = 0; i < 8; i++)
                #pragma unroll
                for (int j = 0; j < 8; j++)
                    acc[i][j] = fmaf(ar[i], br[j], acc[i][j]);
        }
        __syncthreads();
    }
    #pragma unroll
    for (int i = 0; i < 8; i++) {
        const int m = m0 + ty * 8 + i;
        long long rowoff = (long long)z * c_batch + (long long)m * ldc;
        #pragma unroll
        for (int j = 0; j < 8; j += 4) {
            float4 v = make_float4(acc[i][j], acc[i][j + 1], acc[i][j + 2], acc[i][j + 3]);
            *reinterpret_cast<float4*>(&C[rowoff + n0 + tx * 8 + j]) = v;
        }
    }
}

// ---------------- small kernels ----------------
__global__ void gh_kernel(const float* __restrict__ h0, const float* __restrict__ whh,
                          const float* __restrict__ bhh)
{
    int i = blockIdx.x * 256 + threadIdx.x;
    if (i >= PB * D3) return;
    int b = i / D3, e = i % D3;
    float acc = bhh[e];
    const float4* hr = reinterpret_cast<const float4*>(h0 + b * PD);
    const float4* wr = reinterpret_cast<const float4*>(whh + (long long)e * PD);
    #pragma unroll 4
    for (int k = 0; k < PD / 4; k++) {
        float4 a = hr[k], w = wr[k];
        acc = fmaf(a.x, w.x, acc); acc = fmaf(a.y, w.y, acc);
        acc = fmaf(a.z, w.z, acc); acc = fmaf(a.w, w.w, acc);
    }
    g_gh[i] = acc;
}

__global__ void build_x(const float* __restrict__ emb, const float* __restrict__ slot,
                        const int* __restrict__ trg)
{
    int idx = blockIdx.x * 256 + threadIdx.x;
    int d = idx & (PD - 1);
    int m = idx >> 10;
    int s = m >> 6, l = (m >> 3) & 7, b = m & 7;
    float v;
    if (l == 0) v = slot[s * PD + d];
    else {
        int tok = trg[b * (PS * PL) + s * PL + (l - 1)];
        v = emb[(long long)tok * PD + d];
    }
    g_x[idx] = v;
}

__global__ void gru_kernel(const float* __restrict__ bih, const float* __restrict__ h0)
{
    int idx = blockIdx.x * 256 + threadIdx.x;
    int d = idx & (PD - 1);
    int m = idx >> 10;
    int b = m & 7;
    long long gb = (long long)m * D3;
    float ir = g_gi[gb + d]          + bih[d];
    float iz = g_gi[gb + PD + d]     + bih[PD + d];
    float in = g_gi[gb + 2 * PD + d] + bih[2 * PD + d];
    float hr = g_gh[b * D3 + d];
    float hz = g_gh[b * D3 + PD + d];
    float hn = g_gh[b * D3 + 2 * PD + d];
    float r = 1.0f / (1.0f + expf(-(ir + hr)));
    float z = 1.0f / (1.0f + expf(-(iz + hz)));
    float n = tanhf(in + r * hn);
    g_h[idx] = (1.0f - z) * n + z * h0[b * PD + d];
}

__global__ void probs_kernel()
{
    int m = blockIdx.x;
    long long base = (long long)(m >> 3) * (PB * PT) + (long long)(m & 7) * PT;
    int t = threadIdx.x;
    float v0 = g_scores[base + t];
    float v1 = g_scores[base + t + 256];
    float mx = blockMax(fmaxf(v0, v1));
    float e0 = expf(v0 - mx), e1 = expf(v1 - mx);
    float sum = blockSum(e0 + e1);
    float inv = 1.0f / sum;
    g_probs[m * PT + t] = e0 * inv;
    g_probs[m * PT + t + 256] = e1 * inv;
}

__global__ void pgen_kernel(const float* __restrict__ w, const float* __restrict__ wb)
{
    int m = blockIdx.x;
    long long base = (long long)m * PD;
    float p = 0.0f;
    for (int d = threadIdx.x; d < PD; d += 256) {
        p = fmaf(g_h[base + d],   w[d],          p);
        p = fmaf(g_ctx[base + d], w[PD + d],     p);
        p = fmaf(g_x[base + d],   w[2 * PD + d], p);
    }
    p = blockSum(p);
    if (threadIdx.x == 0)
        g_pgen[m] = 1.0f / (1.0f + expf(-(p + wb[0])));
}

// single-pass online softmax over V, scaled by p_gen
__global__ void softmax_v2(float* __restrict__ out)
{
    int o = blockIdx.x;
    long long base = (long long)o * PV;
    int s = o >> 6, b = (o >> 3) & 7, l = o & 7;
    int m = s * 64 + l * 8 + b;
    const float4* src = reinterpret_cast<const float4*>(out + base);
    float mx = -INFINITY, sm = 0.0f;
    for (int i = threadIdx.x; i < PV / 4; i += 256) {
        float4 v = src[i];
        float lm = fmaxf(fmaxf(v.x, v.y), fmaxf(v.z, v.w));
        if (lm > mx) { sm *= expf(mx - lm); mx = lm; }
        sm += expf(v.x - mx) + expf(v.y - mx) + expf(v.z - mx) + expf(v.w - mx);
    }
    __shared__ float smx[256], ssm[256];
    smx[threadIdx.x] = mx; ssm[threadIdx.x] = sm;
    __syncthreads();
    for (int st = 128; st; st >>= 1) {
        if (threadIdx.x < st) {
            float m1 = smx[threadIdx.x], s1 = ssm[threadIdx.x];
            float m2 = smx[threadIdx.x + st], s2 = ssm[threadIdx.x + st];
            float nm = fmaxf(m1, m2);
            smx[threadIdx.x] = nm;
            ssm[threadIdx.x] = s1 * expf(m1 - nm) + s2 * expf(m2 - nm);
        }
        __syncthreads();
    }
    float M = smx[0];
    float sc = g_pgen[m] / ssm[0];
    float4* dst = reinterpret_cast<float4*>(out + base);
    for (int i = threadIdx.x; i < PV / 4; i += 256) {
        float4 v = dst[i];
        v.x = expf(v.x - M) * sc; v.y = expf(v.y - M) * sc;
        v.z = expf(v.z - M) * sc; v.w = expf(v.w - M) * sc;
        dst[i] = v;
    }
}

__global__ void scatter_kernel(float* __restrict__ out, const int* __restrict__ story)
{
    int m = blockIdx.x;
    int t = threadIdx.x;
    int s = m >> 6, l = (m >> 3) & 7, b = m & 7;
    long long obase = (long long)((s * 8 + b) * 8 + l) * (long long)PV;
    float w = 1.0f - g_pgen[m];
    int tok = story[b * PT + t];
    atomicAdd(&out[obase + tok], w * g_probs[m * PT + t]);
}

__global__ void gate_kernel(float* __restrict__ out, const float* __restrict__ wg,
                            const float* __restrict__ bg)
{
    int o = blockIdx.x;
    int s = o / (PB * PG);
    int b = (o % (PB * PG)) / PG;
    int g = o % PG;
    int m = s * 64 + b;
    float p = 0.0f;
    for (int d = threadIdx.x; d < PD; d += 128)
        p = fmaf(g_ctx[(long long)m * PD + d], wg[g * PD + d], p);
    p = blockSum(p);
    if (threadIdx.x == 0) out[OUT_PTR_ELEMS + o] = p + bg[g];
}

// ---------------- launch ----------------
extern "C" void kernel_launch(void* const* d_in, const int* in_sizes, int n_in,
                              void* d_out, int out_size)
{
    const float* enc_h   = (const float*)d_in[0];
    const float* enc_out = (const float*)d_in[1];
    const int*   story   = (const int*)d_in[2];
    const int*   trg     = (const int*)d_in[3];
    const float* emb     = (const float*)d_in[4];
    const float* w_ih    = (const float*)d_in[5];
    const float* w_hh    = (const float*)d_in[6];
    const float* b_ih    = (const float*)d_in[7];
    const float* b_hh    = (const float*)d_in[8];
    const float* w_rw    = (const float*)d_in[9];
    const float* w_rb    = (const float*)d_in[10];
    const float* w_gw    = (const float*)d_in[11];
    const float* w_gb    = (const float*)d_in[12];
    const float* slot    = (const float*)d_in[13];
    float* out = (float*)d_out;

    float *px, *ph, *pgi, *psc, *pcx;
    __nv_bfloat16 *pB2, *pA2h, *pA2x, *pW2;
    cudaGetSymbolAddress((void**)&px,   g_x);
    cudaGetSymbolAddress((void**)&ph,   g_h);
    cudaGetSymbolAddress((void**)&pgi,  g_gi);
    cudaGetSymbolAddress((void**)&psc,  g_scores);
    cudaGetSymbolAddress((void**)&pcx,  g_ctx);
    cudaGetSymbolAddress((void**)&pB2,  g_B2);
    cudaGetSymbolAddress((void**)&pA2h, g_A2h);
    cudaGetSymbolAddress((void**)&pA2x, g_A2x);
    cudaGetSymbolAddress((void**)&pW2,  g_W2);

    cudaFuncSetAttribute(mma_gemm<false>, cudaFuncAttributeMaxDynamicSharedMemorySize, MMA_SMEM);
    cudaFuncSetAttribute(mma_gemm<true>,  cudaFuncAttributeMaxDynamicSharedMemorySize, MMA_SMEM);

    // 1) decoder inputs + splits
    build_x<<<(SLB * PD) / 256, 256>>>(emb, slot, trg);
    split_kernel<<<PV, 256>>>(emb, pB2, PV);
    split_kernel<<<D3, 256>>>(w_ih, pW2, D3);
    split_kernel<<<SLB, 256>>>(px, pA2x, SLB);

    // 2) gh = h0 @ w_hh^T + b_hh
    gh_kernel<<<(PB * D3 + 255) / 256, 256>>>(enc_h, w_hh, b_hh);

    // 3) gi = x @ w_ih^T via HMMA (M=1024, N=3072)
    mma_gemm<false><<<dim3(D3 / 128, SLB / 128), 256, MMA_SMEM>>>(pA2x, pW2, pgi, (long long)D3);

    // 4) GRU combine -> h; split h
    gru_kernel<<<(SLB * PD) / 256, 256>>>(b_ih, enc_h);
    split_kernel<<<SLB, 256>>>(ph, pA2h, SLB);

    // 5) scores (fp32)
    gemm128<true><<<dim3(PT / 128, (PS * PL) / 128, PB), 256>>>(
        ph, PB * PD, PD, enc_out, PD, (long long)PT * PD, psc, PB * PT, PT, PD);

    // 6) probs
    probs_kernel<<<SLB, 256>>>();

    // 7) context (fp32)
    gemm128<false><<<dim3(PD / 128, (PS * PL) / 128, PB), 256>>>(
        psc, PB * PT, PT, enc_out, PD, (long long)PT * PD, pcx, PB * PD, PD, PT);

    // 8) p_gen
    pgen_kernel<<<SLB, 256>>>(w_rw, w_rb);

    // 9) logits = h @ E^T via HMMA, permuted into out (M=1024, N=32000)
    mma_gemm<true><<<dim3(PV / 128, SLB / 128), 256, MMA_SMEM>>>(pA2h, pB2, out, 0);

    // 10) out = p_gen * softmax_v(logits)
    softmax_v2<<<SLB, 256>>>(out);

    // 11) out += (1-p_gen) * scatter(probs)
    scatter_kernel<<<SLB, PT>>>(out, story);

    // 12) gate outputs
    gate_kernel<<<PS * PB * PG, 128>>>(out, w_gw, w_gb);
}

// round 4
// speedup vs baseline: 2.1869x; 1.1794x over previous
#include <cuda_runtime.h>
#include <cuda_bf16.h>
#include <math.h>
#include <stdint.h>

// Problem constants
#define PS   16
#define PB   8
#define PL   8
#define PV   32000
#define PD   1024
#define PT   512
#define PG   3
#define SLB  1024
#define D3   3072
#define OUT_PTR_ELEMS 32768000LL

// ---------------- device scratch ----------------
__device__ float g_x[SLB * PD];
__device__ float g_h[SLB * PD];
__device__ float g_gi[SLB * D3];
__device__ float g_gh[PB * D3];
__device__ float g_scores[SLB * PT];
__device__ float g_probs[SLB * PT];
__device__ float g_ctx[SLB * PD];
__device__ float g_pgen[SLB];
// split-precision bf16 operands: row-major, pitch 2048 (cols [0,1024)=hi, [1024,2048)=lo)
__device__ __nv_bfloat16 g_B2[(long long)PV * 2048];
__device__ __nv_bfloat16 g_A2h[SLB * 2048];
__device__ __nv_bfloat16 g_A2x[SLB * 2048];
__device__ __nv_bfloat16 g_W2[D3 * 2048];

// ---------------- helpers ----------------
__device__ __forceinline__ uint32_t smem_u32(const void* p) {
    uint32_t a;
    asm("{ .reg .u64 t; cvta.to.shared.u64 t, %1; cvt.u32.u64 %0, t; }" : "=r"(a) : "l"(p));
    return a;
}
__device__ __forceinline__ void cp16(uint32_t s, const void* g) {
    asm volatile("cp.async.cg.shared.global [%0], [%1], 16;" :: "r"(s), "l"(g) : "memory");
}
__device__ __forceinline__ void cp_commit() {
    asm volatile("cp.async.commit_group;" ::: "memory");
}
template <int N>
__device__ __forceinline__ void cp_wait() {
    asm volatile("cp.async.wait_group %0;" :: "n"(N) : "memory");
}
__device__ __forceinline__ void mma16816(float& c0, float& c1, float& c2, float& c3,
                                         uint32_t a0, uint32_t a1, uint32_t a2, uint32_t a3,
                                         uint32_t b0, uint32_t b1) {
    asm volatile("mma.sync.aligned.m16n8k16.row.col.f32.bf16.bf16.f32 "
                 "{%0,%1,%2,%3}, {%4,%5,%6,%7}, {%8,%9}, {%0,%1,%2,%3};"
                 : "+f"(c0), "+f"(c1), "+f"(c2), "+f"(c3)
                 : "r"(a0), "r"(a1), "r"(a2), "r"(a3), "r"(b0), "r"(b1));
}
// swizzled byte offset within a 64B-row operand tile
__device__ __forceinline__ uint32_t swz(int r, int kb) {
    return (uint32_t)(r * 64 + ((((kb >> 4) ^ ((r >> 1) & 3)) << 4) | (kb & 15)));
}

// ---------------- reductions ----------------
__device__ __forceinline__ float warpMax(float v) {
    #pragma unroll
    for (int o = 16; o; o >>= 1) v = fmaxf(v, __shfl_xor_sync(0xffffffffu, v, o));
    return v;
}
__device__ __forceinline__ float warpSum(float v) {
    #pragma unroll
    for (int o = 16; o; o >>= 1) v += __shfl_xor_sync(0xffffffffu, v, o);
    return v;
}
__device__ float blockSum(float v) {
    __shared__ float sm[32];
    v = warpSum(v);
    int w = threadIdx.x >> 5, l = threadIdx.x & 31;
    __syncthreads();
    if (l == 0) sm[w] = v;
    __syncthreads();
    int nw = (blockDim.x + 31) >> 5;
    v = (threadIdx.x < nw) ? sm[threadIdx.x] : 0.0f;
    if (w == 0) v = warpSum(v);
    if (threadIdx.x == 0) sm[0] = v;
    __syncthreads();
    return sm[0];
}
__device__ float blockMax(float v) {
    __shared__ float sm[32];
    v = warpMax(v);
    int w = threadIdx.x >> 5, l = threadIdx.x & 31;
    __syncthreads();
    if (l == 0) sm[w] = v;
    __syncthreads();
    int nw = (blockDim.x + 31) >> 5;
    v = (threadIdx.x < nw) ? sm[threadIdx.x] : -INFINITY;
    if (w == 0) v = warpMax(v);
    if (threadIdx.x == 0) sm[0] = v;
    __syncthreads();
    return sm[0];
}

// ---------------- split-precision conversion ----------------
__global__ void split_kernel(const float* __restrict__ src, __nv_bfloat16* __restrict__ dst, int nrow)
{
    long long idx = (long long)blockIdx.x * 256 + threadIdx.x;
    long long tot = (long long)nrow * 256;
    if (idx >= tot) return;
    long long row = idx >> 8;
    int c4 = (int)(idx & 255);
    float4 v = reinterpret_cast<const float4*>(src + row * 1024)[c4];
    __nv_bfloat162 h0 = __floats2bfloat162_rn(v.x, v.y);
    __nv_bfloat162 h1 = __floats2bfloat162_rn(v.z, v.w);
    float2 f0 = __bfloat1622float2(h0);
    float2 f1 = __bfloat1622float2(h1);
    __nv_bfloat162 l0 = __floats2bfloat162_rn(v.x - f0.x, v.y - f0.y);
    __nv_bfloat162 l1 = __floats2bfloat162_rn(v.z - f1.x, v.w - f1.y);
    __nv_bfloat162* dh = reinterpret_cast<__nv_bfloat162*>(dst + row * 2048 + c4 * 4);
    dh[0] = h0; dh[1] = h1;
    __nv_bfloat162* dl = reinterpret_cast<__nv_bfloat162*>(dst + row * 2048 + 1024 + c4 * 4);
    dl[0] = l0; dl[1] = l1;
}

// ---------------- HMMA split-precision GEMM (v2) ----------------
// C[m,n] = A[m,:].B[n,:] in near-fp32 via bf16 split: hi*hi + hi*lo + lo*hi,
// interleaved per k-chunk (all 4 operand halves loaded once per chunk).
// CTA tile 256(m) x 128(n), 512 threads = 16 warps (4m x 4n), warp tile 64x32.
// grid.x = M/256 (fastest -> m-tiles of same n concurrent => B L2 reuse),
// grid.y = N/128.  3-stage cp.async pipeline, 48KB/stage.
#define STAGES 3
#define CHUNKS 32
#define STAGE_BYTES 49152
#define MMA_SMEM (STAGES * STAGE_BYTES)

template <bool PERMUTE>
__global__ void __launch_bounds__(512, 1) mma_gemm(
    const __nv_bfloat16* __restrict__ A2,
    const __nv_bfloat16* __restrict__ B2,
    float* __restrict__ C, long long ldc)
{
    extern __shared__ char smd[];
    const uint32_t sbase = smem_u32(smd);
    const int tid = threadIdx.x;
    const int wid = tid >> 5;
    const int lane = tid & 31;
    const int lr = lane >> 2;
    const int q4 = (lane & 3) * 4;
    const int mr = (wid & 3) * 64;        // warp m offset
    const int nc = (wid >> 2) * 32;       // warp n offset
    const long long m0 = (long long)blockIdx.x * 256;
    const long long n0 = (long long)blockIdx.y * 128;

    float acc[4][4][4];
    #pragma unroll
    for (int i = 0; i < 4; i++)
        #pragma unroll
        for (int j = 0; j < 4; j++)
            #pragma unroll
            for (int k = 0; k < 4; k++) acc[i][j][k] = 0.0f;

    const int rB = tid >> 2, gB = tid & 3;
    const uint32_t soB = (uint32_t)(rB * 64 + ((gB ^ ((rB >> 1) & 3)) << 4));

    auto issue = [&](int c) {
        const int koff = c << 5;
        const uint32_t st = sbase + (uint32_t)((c % STAGES) * STAGE_BYTES);
        #pragma unroll
        for (int i = 0; i < 2; i++) {
            const int idx = tid + i * 512;
            const int r = idx >> 2, g = idx & 3;
            const uint32_t so = (uint32_t)(r * 64 + ((g ^ ((r >> 1) & 3)) << 4));
            const __nv_bfloat16* src = A2 + (m0 + r) * 2048 + koff + g * 8;
            cp16(st + so, src);                     // A hi
            cp16(st + 16384 + so, src + 1024);      // A lo
        }
        {
            const __nv_bfloat16* src = B2 + (n0 + rB) * 2048 + koff + gB * 8;
            cp16(st + 32768 + soB, src);            // B hi
            cp16(st + 40960 + soB, src + 1024);     // B lo
        }
        cp_commit();
    };

    issue(0); issue(1);

    #pragma unroll 1
    for (int c = 0; c < CHUNKS; c++) {
        cp_wait<STAGES - 2>();
        __syncthreads();
        if (c + 2 < CHUNKS) issue(c + 2);

        const char* st = smd + (c % STAGES) * STAGE_BYTES;
        const char* Ahi = st;
        const char* Alo = st + 16384;
        const char* Bhi = st + 32768;
        const char* Blo = st + 40960;

        #pragma unroll
        for (int kc2 = 0; kc2 < 2; kc2++) {
            const int kb0 = kc2 * 32 + q4;
            uint32_t ah[4][4], al[4][4], bh[4][2], bl[4][2];
            #pragma unroll
            for (int fm = 0; fm < 4; fm++) {
                const int r = mr + fm * 16 + lr;
                const uint32_t o0 = swz(r, kb0), o1 = swz(r + 8, kb0);
                const uint32_t o2 = swz(r, kb0 + 16), o3 = swz(r + 8, kb0 + 16);
                ah[fm][0] = *(const uint32_t*)(Ahi + o0);
                ah[fm][1] = *(const uint32_t*)(Ahi + o1);
                ah[fm][2] = *(const uint32_t*)(Ahi + o2);
                ah[fm][3] = *(const uint32_t*)(Ahi + o3);
                al[fm][0] = *(const uint32_t*)(Alo + o0);
                al[fm][1] = *(const uint32_t*)(Alo + o1);
                al[fm][2] = *(const uint32_t*)(Alo + o2);
                al[fm][3] = *(const uint32_t*)(Alo + o3);
            }
            #pragma unroll
            for (int fn = 0; fn < 4; fn++) {
                const int n = nc + fn * 8 + lr;
                const uint32_t o0 = swz(n, kb0), o1 = swz(n, kb0 + 16);
                bh[fn][0] = *(const uint32_t*)(Bhi + o0);
                bh[fn][1] = *(const uint32_t*)(Bhi + o1);
                bl[fn][0] = *(const uint32_t*)(Blo + o0);
                bl[fn][1] = *(const uint32_t*)(Blo + o1);
            }
            #pragma unroll
            for (int fm = 0; fm < 4; fm++)
                #pragma unroll
                for (int fn = 0; fn < 4; fn++) {
                    mma16816(acc[fm][fn][0], acc[fm][fn][1], acc[fm][fn][2], acc[fm][fn][3],
                             ah[fm][0], ah[fm][1], ah[fm][2], ah[fm][3], bh[fn][0], bh[fn][1]);
                    mma16816(acc[fm][fn][0], acc[fm][fn][1], acc[fm][fn][2], acc[fm][fn][3],
                             ah[fm][0], ah[fm][1], ah[fm][2], ah[fm][3], bl[fn][0], bl[fn][1]);
                    mma16816(acc[fm][fn][0], acc[fm][fn][1], acc[fm][fn][2], acc[fm][fn][3],
                             al[fm][0], al[fm][1], al[fm][2], al[fm][3], bh[fn][0], bh[fn][1]);
                }
        }
    }

    // epilogue
    #pragma unroll
    for (int fm = 0; fm < 4; fm++) {
        const int mrow0 = (int)m0 + mr + fm * 16 + lr;
        const int mrow1 = mrow0 + 8;
        long long ro0, ro1;
        if (PERMUTE) {
            int s0 = mrow0 >> 6, l0 = (mrow0 >> 3) & 7, b0 = mrow0 & 7;
            int s1 = mrow1 >> 6, l1 = (mrow1 >> 3) & 7, b1 = mrow1 & 7;
            ro0 = (long long)((s0 * 8 + b0) * 8 + l0) * (long long)PV;
            ro1 = (long long)((s1 * 8 + b1) * 8 + l1) * (long long)PV;
        } else {
            ro0 = (long long)mrow0 * ldc;
            ro1 = (long long)mrow1 * ldc;
        }
        #pragma unroll
        for (int fn = 0; fn < 4; fn++) {
            const long long col = n0 + nc + fn * 8 + (lane & 3) * 2;
            *reinterpret_cast<float2*>(C + ro0 + col) = make_float2(acc[fm][fn][0], acc[fm][fn][1]);
            *reinterpret_cast<float2*>(C + ro1 + col) = make_float2(acc[fm][fn][2], acc[fm][fn][3]);
        }
    }
}

// ---------------- fp32 tiled SGEMM (scores/context) ----------------
template <bool TRANSB>
__global__ void gemm128(const float* __restrict__ A, int lda, long long a_batch,
                        const float* __restrict__ B, int ldb, long long b_batch,
                        float* __restrict__ C, int ldc, long long c_batch,
                        int K)
{
    __shared__ float As[8][128];
    __shared__ float Bs[8][128];
    const int z = blockIdx.z;
    const float* Ab = A + (long long)z * a_batch;
    const float* Bb = B + (long long)z * b_batch;
    const int m0 = blockIdx.y * 128;
    const int n0 = blockIdx.x * 128;
    const int tid = threadIdx.x;
    const int tx = tid & 15;
    const int ty = tid >> 4;
    float acc[8][8];
    #pragma unroll
    for (int i = 0; i < 8; i++)
        #pragma unroll
        for (int j = 0; j < 8; j++) acc[i][j] = 0.0f;
    const int arow = tid >> 1;
    const int acol = (tid & 1) * 4;
    const int krow = tid >> 5;
    const int ncol = (tid & 31) * 4;
    for (int k0 = 0; k0 < K; k0 += 8) {
        float4 av = *reinterpret_cast<const float4*>(&Ab[(long long)(m0 + arow) * lda + k0 + acol]);
        As[acol + 0][arow] = av.x; As[acol + 1][arow] = av.y;
        As[acol + 2][arow] = av.z; As[acol + 3][arow] = av.w;
        if (TRANSB) {
            float4 bv = *reinterpret_cast<const float4*>(&Bb[(long long)(n0 + arow) * ldb + k0 + acol]);
            Bs[acol + 0][arow] = bv.x; Bs[acol + 1][arow] = bv.y;
            Bs[acol + 2][arow] = bv.z; Bs[acol + 3][arow] = bv.w;
        } else {
            float4 bv = *reinterpret_cast<const float4*>(&Bb[(long long)(k0 + krow) * ldb + n0 + ncol]);
            *reinterpret_cast<float4*>(&Bs[krow][ncol]) = bv;
        }
        __syncthreads();
        #pragma unroll
        for (int kk = 0; kk < 8; kk++) {
            float ar[8], br[8];
            *reinterpret_cast<float4*>(&ar[0]) = *reinterpret_cast<float4*>(&As[kk][ty * 8]);
            *reinterpret_cast<float4*>(&ar[4]) = *reinterpret_cast<float4*>(&As[kk][ty * 8 + 4]);
            *reinterpret_cast<float4*>(&br[0]) = *reinterpret_cast<float4*>(&Bs[kk][tx * 8]);
            *reinterpret_cast<float4*>(&br[4]) = *reinterpret_cast<float4*>(&Bs[kk][tx * 8 + 4]);
            #pragma unroll
            for (int i = 0; i < 8; i++)
                #pragma unroll
                for (int j = 0; j < 8; j++)
                    acc[i][j] = fmaf(ar[i], br[j], acc[i][j]);
        }
        __syncthreads();
    }
    #pragma unroll
    for (int i = 0; i < 8; i++) {
        const int m = m0 + ty * 8 + i;
        long long rowoff = (long long)z * c_batch + (long long)m * ldc;
        #pragma unroll
        for (int j = 0; j < 8; j += 4) {
            float4 v = make_float4(acc[i][j], acc[i][j + 1], acc[i][j + 2], acc[i][j + 3]);
            *reinterpret_cast<float4*>(&C[rowoff + n0 + tx * 8 + j]) = v;
        }
    }
}

// ---------------- small kernels ----------------
__global__ void gh_kernel(const float* __restrict__ h0, const float* __restrict__ whh,
                          const float* __restrict__ bhh)
{
    int i = blockIdx.x * 256 + threadIdx.x;
    if (i >= PB * D3) return;
    int b = i / D3, e = i % D3;
    float acc = bhh[e];
    const float4* hr = reinterpret_cast<const float4*>(h0 + b * PD);
    const float4* wr = reinterpret_cast<const float4*>(whh + (long long)e * PD);
    #pragma unroll 4
    for (int k = 0; k < PD / 4; k++) {
        float4 a = hr[k], w = wr[k];
        acc = fmaf(a.x, w.x, acc); acc = fmaf(a.y, w.y, acc);
        acc = fmaf(a.z, w.z, acc); acc = fmaf(a.w, w.w, acc);
    }
    g_gh[i] = acc;
}

__global__ void build_x(const float* __restrict__ emb, const float* __restrict__ slot,
                        const int* __restrict__ trg)
{
    int idx = blockIdx.x * 256 + threadIdx.x;
    int d = idx & (PD - 1);
    int m = idx >> 10;
    int s = m >> 6, l = (m >> 3) & 7, b = m & 7;
    float v;
    if (l == 0) v = slot[s * PD + d];
    else {
        int tok = trg[b * (PS * PL) + s * PL + (l - 1)];
        v = emb[(long long)tok * PD + d];
    }
    g_x[idx] = v;
}

__global__ void gru_kernel(const float* __restrict__ bih, const float* __restrict__ h0)
{
    int idx = blockIdx.x * 256 + threadIdx.x;
    int d = idx & (PD - 1);
    int m = idx >> 10;
    int b = m & 7;
    long long gb = (long long)m * D3;
    float ir = g_gi[gb + d]          + bih[d];
    float iz = g_gi[gb + PD + d]     + bih[PD + d];
    float in = g_gi[gb + 2 * PD + d] + bih[2 * PD + d];
    float hr = g_gh[b * D3 + d];
    float hz = g_gh[b * D3 + PD + d];
    float hn = g_gh[b * D3 + 2 * PD + d];
    float r = 1.0f / (1.0f + expf(-(ir + hr)));
    float z = 1.0f / (1.0f + expf(-(iz + hz)));
    float n = tanhf(in + r * hn);
    g_h[idx] = (1.0f - z) * n + z * h0[b * PD + d];
}

__global__ void probs_kernel()
{
    int m = blockIdx.x;
    long long base = (long long)(m >> 3) * (PB * PT) + (long long)(m & 7) * PT;
    int t = threadIdx.x;
    float v0 = g_scores[base + t];
    float v1 = g_scores[base + t + 256];
    float mx = blockMax(fmaxf(v0, v1));
    float e0 = expf(v0 - mx), e1 = expf(v1 - mx);
    float sum = blockSum(e0 + e1);
    float inv = 1.0f / sum;
    g_probs[m * PT + t] = e0 * inv;
    g_probs[m * PT + t + 256] = e1 * inv;
}

__global__ void pgen_kernel(const float* __restrict__ w, const float* __restrict__ wb)
{
    int m = blockIdx.x;
    long long base = (long long)m * PD;
    float p = 0.0f;
    for (int d = threadIdx.x; d < PD; d += 256) {
        p = fmaf(g_h[base + d],   w[d],          p);
        p = fmaf(g_ctx[base + d], w[PD + d],     p);
        p = fmaf(g_x[base + d],   w[2 * PD + d], p);
    }
    p = blockSum(p);
    if (threadIdx.x == 0)
        g_pgen[m] = 1.0f / (1.0f + expf(-(p + wb[0])));
}

// single-pass online softmax over V, scaled by p_gen
__global__ void softmax_v2(float* __restrict__ out)
{
    int o = blockIdx.x;
    long long base = (long long)o * PV;
    int s = o >> 6, b = (o >> 3) & 7, l = o & 7;
    int m = s * 64 + l * 8 + b;
    const float4* src = reinterpret_cast<const float4*>(out + base);
    float mx = -INFINITY, sm = 0.0f;
    for (int i = threadIdx.x; i < PV / 4; i += 256) {
        float4 v = src[i];
        float lm = fmaxf(fmaxf(v.x, v.y), fmaxf(v.z, v.w));
        if (lm > mx) { sm *= expf(mx - lm); mx = lm; }
        sm += expf(v.x - mx) + expf(v.y - mx) + expf(v.z - mx) + expf(v.w - mx);
    }
    __shared__ float smx[256], ssm[256];
    smx[threadIdx.x] = mx; ssm[threadIdx.x] = sm;
    __syncthreads();
    for (int st = 128; st; st >>= 1) {
        if (threadIdx.x < st) {
            float m1 = smx[threadIdx.x], s1 = ssm[threadIdx.x];
            float m2 = smx[threadIdx.x + st], s2 = ssm[threadIdx.x + st];
            float nm = fmaxf(m1, m2);
            smx[threadIdx.x] = nm;
            ssm[threadIdx.x] = s1 * expf(m1 - nm) + s2 * expf(m2 - nm);
        }
        __syncthreads();
    }
    float M = smx[0];
    float sc = g_pgen[m] / ssm[0];
    float4* dst = reinterpret_cast<float4*>(out + base);
    for (int i = threadIdx.x; i < PV / 4; i += 256) {
        float4 v = dst[i];
        v.x = expf(v.x - M) * sc; v.y = expf(v.y - M) * sc;
        v.z = expf(v.z - M) * sc; v.w = expf(v.w - M) * sc;
        dst[i] = v;
    }
}

__global__ void scatter_kernel(float* __restrict__ out, const int* __restrict__ story)
{
    int m = blockIdx.x;
    int t = threadIdx.x;
    int s = m >> 6, l = (m >> 3) & 7, b = m & 7;
    long long obase = (long long)((s * 8 + b) * 8 + l) * (long long)PV;
    float w = 1.0f - g_pgen[m];
    int tok = story[b * PT + t];
    atomicAdd(&out[obase + tok], w * g_probs[m * PT + t]);
}

__global__ void gate_kernel(float* __restrict__ out, const float* __restrict__ wg,
                            const float* __restrict__ bg)
{
    int o = blockIdx.x;
    int s = o / (PB * PG);
    int b = (o % (PB * PG)) / PG;
    int g = o % PG;
    int m = s * 64 + b;
    float p = 0.0f;
    for (int d = threadIdx.x; d < PD; d += 128)
        p = fmaf(g_ctx[(long long)m * PD + d], wg[g * PD + d], p);
    p = blockSum(p);
    if (threadIdx.x == 0) out[OUT_PTR_ELEMS + o] = p + bg[g];
}

// ---------------- launch ----------------
extern "C" void kernel_launch(void* const* d_in, const int* in_sizes, int n_in,
                              void* d_out, int out_size)
{
    const float* enc_h   = (const float*)d_in[0];
    const float* enc_out = (const float*)d_in[1];
    const int*   story   = (const int*)d_in[2];
    const int*   trg     = (const int*)d_in[3];
    const float* emb     = (const float*)d_in[4];
    const float* w_ih    = (const float*)d_in[5];
    const float* w_hh    = (const float*)d_in[6];
    const float* b_ih    = (const float*)d_in[7];
    const float* b_hh    = (const float*)d_in[8];
    const float* w_rw    = (const float*)d_in[9];
    const float* w_rb    = (const float*)d_in[10];
    const float* w_gw    = (const float*)d_in[11];
    const float* w_gb    = (const float*)d_in[12];
    const float* slot    = (const float*)d_in[13];
    float* out = (float*)d_out;

    float *px, *ph, *pgi, *psc, *pcx;
    __nv_bfloat16 *pB2, *pA2h, *pA2x, *pW2;
    cudaGetSymbolAddress((void**)&px,   g_x);
    cudaGetSymbolAddress((void**)&ph,   g_h);
    cudaGetSymbolAddress((void**)&pgi,  g_gi);
    cudaGetSymbolAddress((void**)&psc,  g_scores);
    cudaGetSymbolAddress((void**)&pcx,  g_ctx);
    cudaGetSymbolAddress((void**)&pB2,  g_B2);
    cudaGetSymbolAddress((void**)&pA2h, g_A2h);
    cudaGetSymbolAddress((void**)&pA2x, g_A2x);
    cudaGetSymbolAddress((void**)&pW2,  g_W2);

    cudaFuncSetAttribute(mma_gemm<false>, cudaFuncAttributeMaxDynamicSharedMemorySize, MMA_SMEM);
    cudaFuncSetAttribute(mma_gemm<true>,  cudaFuncAttributeMaxDynamicSharedMemorySize, MMA_SMEM);

    // 1) decoder inputs + splits
    build_x<<<(SLB * PD) / 256, 256>>>(emb, slot, trg);
    split_kernel<<<PV, 256>>>(emb, pB2, PV);
    split_kernel<<<D3, 256>>>(w_ih, pW2, D3);
    split_kernel<<<SLB, 256>>>(px, pA2x, SLB);

    // 2) gh = h0 @ w_hh^T + b_hh
    gh_kernel<<<(PB * D3 + 255) / 256, 256>>>(enc_h, w_hh, b_hh);

    // 3) gi = x @ w_ih^T via HMMA (M=1024, N=3072): grid (m-tiles, n-tiles)
    mma_gemm<false><<<dim3(SLB / 256, D3 / 128), 512, MMA_SMEM>>>(pA2x, pW2, pgi, (long long)D3);

    // 4) GRU combine -> h; split h
    gru_kernel<<<(SLB * PD) / 256, 256>>>(b_ih, enc_h);
    split_kernel<<<SLB, 256>>>(ph, pA2h, SLB);

    // 5) scores (fp32)
    gemm128<true><<<dim3(PT / 128, (PS * PL) / 128, PB), 256>>>(
        ph, PB * PD, PD, enc_out, PD, (long long)PT * PD, psc, PB * PT, PT, PD);

    // 6) probs
    probs_kernel<<<SLB, 256>>>();

    // 7) context (fp32)
    gemm128<false><<<dim3(PD / 128, (PS * PL) / 128, PB), 256>>>(
        psc, PB * PT, PT, enc_out, PD, (long long)PT * PD, pcx, PB * PD, PD, PT);

    // 8) p_gen
    pgen_kernel<<<SLB, 256>>>(w_rw, w_rb);

    // 9) logits = h @ E^T via HMMA, permuted into out (M=1024, N=32000)
    mma_gemm<true><<<dim3(SLB / 256, PV / 128), 512, MMA_SMEM>>>(pA2h, pB2, out, 0);

    // 10) out = p_gen * softmax_v(logits)
    softmax_v2<<<SLB, 256>>>(out);

    // 11) out += (1-p_gen) * scatter(probs)
    scatter_kernel<<<SLB, PT>>>(out, story);

    // 12) gate outputs
    gate_kernel<<<PS * PB * PG, 128>>>(out, w_gw, w_gb);
}

// round 5
// speedup vs baseline: 2.9196x; 1.3351x over previous
#include <cuda_runtime.h>
#include <cuda_bf16.h>
#include <math.h>
#include <stdint.h>

// Problem constants
#define PS   16
#define PB   8
#define PL   8
#define PV   32000
#define PD   1024
#define PT   512
#define PG   3
#define SLB  1024
#define D3   3072
#define OUT_PTR_ELEMS 32768000LL

// ---------------- device scratch ----------------
__device__ float g_x[SLB * PD];
__device__ float g_h[SLB * PD];
__device__ float g_gi[SLB * D3];
__device__ float g_gh[PB * D3];
__device__ float g_scores[SLB * PT];   // [m][t], m = slrow*8+b
__device__ float g_probs[SLB * PT];
__device__ float g_ctx[SLB * PD];
__device__ float g_pgen[SLB];
// split bf16 operands, pitch 2K: [0,K)=hi, [K,2K)=lo
__device__ __nv_bfloat16 g_B2[(long long)PV * 2048];    // embedding   K=1024
__device__ __nv_bfloat16 g_A2h[SLB * 2048];             // h           K=1024
__device__ __nv_bfloat16 g_A2x[SLB * 2048];             // x           K=1024
__device__ __nv_bfloat16 g_W2[D3 * 2048];               // w_ih        K=1024
__device__ __nv_bfloat16 g_E2[(long long)PB * PT * 2048];   // enc (t rows, d cols) K=1024
__device__ __nv_bfloat16 g_ET2[(long long)PB * PD * 1024];  // enc^T (d rows, t cols) K=512
__device__ __nv_bfloat16 g_S2[SLB * 1024];              // scores      K=512

// ---------------- helpers ----------------
__device__ __forceinline__ uint32_t smem_u32(const void* p) {
    uint32_t a;
    asm("{ .reg .u64 t; cvta.to.shared.u64 t, %1; cvt.u32.u64 %0, t; }" : "=r"(a) : "l"(p));
    return a;
}
__device__ __forceinline__ void cp16(uint32_t s, const void* g) {
    asm volatile("cp.async.cg.shared.global [%0], [%1], 16;" :: "r"(s), "l"(g) : "memory");
}
__device__ __forceinline__ void cp_commit() {
    asm volatile("cp.async.commit_group;" ::: "memory");
}
template <int N>
__device__ __forceinline__ void cp_wait() {
    asm volatile("cp.async.wait_group %0;" :: "n"(N) : "memory");
}
__device__ __forceinline__ void mma16816(float& c0, float& c1, float& c2, float& c3,
                                         uint32_t a0, uint32_t a1, uint32_t a2, uint32_t a3,
                                         uint32_t b0, uint32_t b1) {
    asm volatile("mma.sync.aligned.m16n8k16.row.col.f32.bf16.bf16.f32 "
                 "{%0,%1,%2,%3}, {%4,%5,%6,%7}, {%8,%9}, {%0,%1,%2,%3};"
                 : "+f"(c0), "+f"(c1), "+f"(c2), "+f"(c3)
                 : "r"(a0), "r"(a1), "r"(a2), "r"(a3), "r"(b0), "r"(b1));
}
__device__ __forceinline__ uint32_t swz(int r, int kb) {
    return (uint32_t)(r * 64 + ((((kb >> 4) ^ ((r >> 1) & 3)) << 4) | (kb & 15)));
}
__device__ __forceinline__ void split2(float v, __nv_bfloat16& hi, __nv_bfloat16& lo) {
    hi = __float2bfloat16(v);
    lo = __float2bfloat16(v - __bfloat162float(hi));
}

// ---------------- reductions ----------------
__device__ __forceinline__ float warpMax(float v) {
    #pragma unroll
    for (int o = 16; o; o >>= 1) v = fmaxf(v, __shfl_xor_sync(0xffffffffu, v, o));
    return v;
}
__device__ __forceinline__ float warpSum(float v) {
    #pragma unroll
    for (int o = 16; o; o >>= 1) v += __shfl_xor_sync(0xffffffffu, v, o);
    return v;
}
__device__ float blockSum(float v) {
    __shared__ float sm[32];
    v = warpSum(v);
    int w = threadIdx.x >> 5, l = threadIdx.x & 31;
    __syncthreads();
    if (l == 0) sm[w] = v;
    __syncthreads();
    int nw = (blockDim.x + 31) >> 5;
    v = (threadIdx.x < nw) ? sm[threadIdx.x] : 0.0f;
    if (w == 0) v = warpSum(v);
    if (threadIdx.x == 0) sm[0] = v;
    __syncthreads();
    return sm[0];
}
__device__ float blockMax(float v) {
    __shared__ float sm[32];
    v = warpMax(v);
    int w = threadIdx.x >> 5, l = threadIdx.x & 31;
    __syncthreads();
    if (l == 0) sm[w] = v;
    __syncthreads();
    int nw = (blockDim.x + 31) >> 5;
    v = (threadIdx.x < nw) ? sm[threadIdx.x] : -INFINITY;
    if (w == 0) v = warpMax(v);
    if (threadIdx.x == 0) sm[0] = v;
    __syncthreads();
    return sm[0];
}

// ---------------- split kernels ----------------
// contiguous rows of length K = 4<<k4shift; dst pitch 2K
__global__ void split_generic(const float* __restrict__ src, __nv_bfloat16* __restrict__ dst,
                              int k4shift, long long total4)
{
    long long idx = (long long)blockIdx.x * 256 + threadIdx.x;
    if (idx >= total4) return;
    long long row = idx >> k4shift;
    int c4 = (int)(idx & ((1 << k4shift) - 1));
    int K = 4 << k4shift;
    float4 v = reinterpret_cast<const float4*>(src)[idx];
    __nv_bfloat162 h0 = __floats2bfloat162_rn(v.x, v.y);
    __nv_bfloat162 h1 = __floats2bfloat162_rn(v.z, v.w);
    float2 f0 = __bfloat1622float2(h0);
    float2 f1 = __bfloat1622float2(h1);
    __nv_bfloat162 l0 = __floats2bfloat162_rn(v.x - f0.x, v.y - f0.y);
    __nv_bfloat162 l1 = __floats2bfloat162_rn(v.z - f1.x, v.w - f1.y);
    long long base = row * (2LL * K);
    __nv_bfloat162* dh = reinterpret_cast<__nv_bfloat162*>(dst + base + c4 * 4);
    dh[0] = h0; dh[1] = h1;
    __nv_bfloat162* dl = reinterpret_cast<__nv_bfloat162*>(dst + base + K + c4 * 4);
    dl[0] = l0; dl[1] = l1;
}

// enc (B,T,D) -> ET2[(b*D+d)][t hi | t lo], pitch 1024
__global__ void trans_split(const float* __restrict__ enc, __nv_bfloat16* __restrict__ dst)
{
    __shared__ float tile[32][33];
    int b = blockIdx.z;
    int d0 = blockIdx.y * 32;
    int t0 = blockIdx.x * 32;
    int tx = threadIdx.x, ty = threadIdx.y;   // 32 x 8
    const float* src = enc + ((long long)b * PT + t0) * PD + d0;
    #pragma unroll
    for (int j = 0; j < 4; j++)
        tile[ty + j * 8][tx] = src[(ty + j * 8) * PD + tx];
    __syncthreads();
    #pragma unroll
    for (int j = 0; j < 4; j++) {
        int d = d0 + ty + j * 8;
        float v = tile[tx][ty + j * 8];
        __nv_bfloat16 hi, lo; split2(v, hi, lo);
        long long ro = ((long long)(b << 10) + d) * 1024 + t0 + tx;
        dst[ro] = hi;
        dst[ro + 512] = lo;
    }
}

// ---------------- unified HMMA split-precision GEMM ----------------
// C[z,m,n] = A[z,m,:].B[z,n,:] via bf16 split (hh + hl + lh), fp32 accum.
// CTA tile 128x128, 256 threads (8 warps 2m x 4n, warp 64x32), k-chunk 32,
// 3-stage cp.async, 32KB/stage -> 2 CTAs/SM.
#define STAGE_B 32768
#define MMA_SMEM (3 * STAGE_B)

template <bool PERMUTE>
__global__ void __launch_bounds__(256, 2) mma_gemm(
    const __nv_bfloat16* __restrict__ A2, long long a_rs, long long a_batch,
    const __nv_bfloat16* __restrict__ B2, long long b_rs, long long b_batch,
    float* __restrict__ C, long long c_rs, long long c_batch,
    int K)
{
    extern __shared__ char smd[];
    const uint32_t sbase = smem_u32(smd);
    const int tid = threadIdx.x;
    const int wid = tid >> 5;
    const int lane = tid & 31;
    const int lr = lane >> 2;
    const int q4 = (lane & 3) * 4;
    const int mr = (wid & 1) * 64;
    const int nc = (wid >> 1) * 32;
    const long long m0 = (long long)blockIdx.x * 128;
    const long long n0 = (long long)blockIdx.y * 128;
    const int z = blockIdx.z;
    const __nv_bfloat16* Ab = A2 + (long long)z * a_batch;
    const __nv_bfloat16* Bb = B2 + (long long)z * b_batch;
    const int CH = K >> 5;

    float acc[4][4][4];
    #pragma unroll
    for (int i = 0; i < 4; i++)
        #pragma unroll
        for (int j = 0; j < 4; j++)
            #pragma unroll
            for (int k = 0; k < 4; k++) acc[i][j][k] = 0.0f;

    auto issue = [&](int c) {
        const int koff = c << 5;
        const uint32_t st = sbase + (uint32_t)((c % 3) * STAGE_B);
        #pragma unroll
        for (int i = 0; i < 2; i++) {
            const int idx = tid + i * 256;
            const int r = idx >> 2, g = idx & 3;
            const uint32_t so = (uint32_t)(r * 64 + ((g ^ ((r >> 1) & 3)) << 4));
            const __nv_bfloat16* a = Ab + (m0 + r) * a_rs + koff + g * 8;
            cp16(st + so, a);
            cp16(st + 8192 + so, a + K);
            const __nv_bfloat16* b = Bb + (n0 + r) * b_rs + koff + g * 8;
            cp16(st + 16384 + so, b);
            cp16(st + 24576 + so, b + K);
        }
        cp_commit();
    };

    issue(0); issue(1);

    #pragma unroll 1
    for (int c = 0; c < CH; c++) {
        cp_wait<1>();
        __syncthreads();
        if (c + 2 < CH) issue(c + 2);

        const char* st = smd + (c % 3) * STAGE_B;
        const char* Ahi = st;
        const char* Alo = st + 8192;
        const char* Bhi = st + 16384;
        const char* Blo = st + 24576;

        #pragma unroll
        for (int kc2 = 0; kc2 < 2; kc2++) {
            const int kb0 = kc2 * 32 + q4;
            uint32_t ah[4][4], al[4][4], bh[4][2], bl[4][2];
            #pragma unroll
            for (int fm = 0; fm < 4; fm++) {
                const int r = mr + fm * 16 + lr;
                const uint32_t o0 = swz(r, kb0), o1 = swz(r + 8, kb0);
                const uint32_t o2 = swz(r, kb0 + 16), o3 = swz(r + 8, kb0 + 16);
                ah[fm][0] = *(const uint32_t*)(Ahi + o0);
                ah[fm][1] = *(const uint32_t*)(Ahi + o1);
                ah[fm][2] = *(const uint32_t*)(Ahi + o2);
                ah[fm][3] = *(const uint32_t*)(Ahi + o3);
                al[fm][0] = *(const uint32_t*)(Alo + o0);
                al[fm][1] = *(const uint32_t*)(Alo + o1);
                al[fm][2] = *(const uint32_t*)(Alo + o2);
                al[fm][3] = *(const uint32_t*)(Alo + o3);
            }
            #pragma unroll
            for (int fn = 0; fn < 4; fn++) {
                const int n = nc + fn * 8 + lr;
                const uint32_t o0 = swz(n, kb0), o1 = swz(n, kb0 + 16);
                bh[fn][0] = *(const uint32_t*)(Bhi + o0);
                bh[fn][1] = *(const uint32_t*)(Bhi + o1);
                bl[fn][0] = *(const uint32_t*)(Blo + o0);
                bl[fn][1] = *(const uint32_t*)(Blo + o1);
            }
            #pragma unroll
            for (int fm = 0; fm < 4; fm++)
                #pragma unroll
                for (int fn = 0; fn < 4; fn++) {
                    mma16816(acc[fm][fn][0], acc[fm][fn][1], acc[fm][fn][2], acc[fm][fn][3],
                             ah[fm][0], ah[fm][1], ah[fm][2], ah[fm][3], bh[fn][0], bh[fn][1]);
                    mma16816(acc[fm][fn][0], acc[fm][fn][1], acc[fm][fn][2], acc[fm][fn][3],
                             ah[fm][0], ah[fm][1], ah[fm][2], ah[fm][3], bl[fn][0], bl[fn][1]);
                    mma16816(acc[fm][fn][0], acc[fm][fn][1], acc[fm][fn][2], acc[fm][fn][3],
                             al[fm][0], al[fm][1], al[fm][2], al[fm][3], bh[fn][0], bh[fn][1]);
                }
        }
    }

    // epilogue
    #pragma unroll
    for (int fm = 0; fm < 4; fm++) {
        const int mrow0 = (int)m0 + mr + fm * 16 + lr;
        const int mrow1 = mrow0 + 8;
        long long ro0, ro1;
        if (PERMUTE) {
            int s0 = mrow0 >> 6, l0 = (mrow0 >> 3) & 7, b0 = mrow0 & 7;
            int s1 = mrow1 >> 6, l1 = (mrow1 >> 3) & 7, b1 = mrow1 & 7;
            ro0 = (long long)((s0 * 8 + b0) * 8 + l0) * (long long)PV;
            ro1 = (long long)((s1 * 8 + b1) * 8 + l1) * (long long)PV;
        } else {
            ro0 = (long long)z * c_batch + (long long)mrow0 * c_rs;
            ro1 = (long long)z * c_batch + (long long)mrow1 * c_rs;
        }
        #pragma unroll
        for (int fn = 0; fn < 4; fn++) {
            const long long col = n0 + nc + fn * 8 + (lane & 3) * 2;
            *reinterpret_cast<float2*>(C + ro0 + col) = make_float2(acc[fm][fn][0], acc[fm][fn][1]);
            *reinterpret_cast<float2*>(C + ro1 + col) = make_float2(acc[fm][fn][2], acc[fm][fn][3]);
        }
    }
}

// ---------------- small kernels ----------------
__global__ void gh_kernel(const float* __restrict__ h0, const float* __restrict__ whh,
                          const float* __restrict__ bhh)
{
    int i = blockIdx.x * 256 + threadIdx.x;
    if (i >= PB * D3) return;
    int b = i / D3, e = i % D3;
    float acc = bhh[e];
    const float4* hr = reinterpret_cast<const float4*>(h0 + b * PD);
    const float4* wr = reinterpret_cast<const float4*>(whh + (long long)e * PD);
    #pragma unroll 4
    for (int k = 0; k < PD / 4; k++) {
        float4 a = hr[k], w = wr[k];
        acc = fmaf(a.x, w.x, acc); acc = fmaf(a.y, w.y, acc);
        acc = fmaf(a.z, w.z, acc); acc = fmaf(a.w, w.w, acc);
    }
    g_gh[i] = acc;
}

// x + fused split
__global__ void build_x(const float* __restrict__ emb, const float* __restrict__ slot,
                        const int* __restrict__ trg)
{
    int idx = blockIdx.x * 256 + threadIdx.x;
    int d = idx & (PD - 1);
    int m = idx >> 10;
    int s = m >> 6, l = (m >> 3) & 7, b = m & 7;
    float v;
    if (l == 0) v = slot[s * PD + d];
    else {
        int tok = trg[b * (PS * PL) + s * PL + (l - 1)];
        v = emb[(long long)tok * PD + d];
    }
    g_x[idx] = v;
    __nv_bfloat16 hi, lo; split2(v, hi, lo);
    g_A2x[m * 2048 + d] = hi;
    g_A2x[m * 2048 + 1024 + d] = lo;
}

// GRU combine + fused split of h
__global__ void gru_kernel(const float* __restrict__ bih, const float* __restrict__ h0)
{
    int idx = blockIdx.x * 256 + threadIdx.x;
    int d = idx & (PD - 1);
    int m = idx >> 10;
    int b = m & 7;
    long long gb = (long long)m * D3;
    float ir = g_gi[gb + d]          + bih[d];
    float iz = g_gi[gb + PD + d]     + bih[PD + d];
    float in = g_gi[gb + 2 * PD + d] + bih[2 * PD + d];
    float hr = g_gh[b * D3 + d];
    float hz = g_gh[b * D3 + PD + d];
    float hn = g_gh[b * D3 + 2 * PD + d];
    float r = 1.0f / (1.0f + expf(-(ir + hr)));
    float z = 1.0f / (1.0f + expf(-(iz + hz)));
    float n = tanhf(in + r * hn);
    float h = (1.0f - z) * n + z * h0[b * PD + d];
    g_h[idx] = h;
    __nv_bfloat16 hi, lo; split2(h, hi, lo);
    g_A2h[m * 2048 + d] = hi;
    g_A2h[m * 2048 + 1024 + d] = lo;
}

__global__ void probs_kernel()
{
    int m = blockIdx.x;
    long long base = (long long)m * PT;
    int t = threadIdx.x;
    float v0 = g_scores[base + t];
    float v1 = g_scores[base + t + 256];
    float mx = blockMax(fmaxf(v0, v1));
    float e0 = expf(v0 - mx), e1 = expf(v1 - mx);
    float sum = blockSum(e0 + e1);
    float inv = 1.0f / sum;
    g_probs[base + t] = e0 * inv;
    g_probs[base + t + 256] = e1 * inv;
}

__global__ void pgen_kernel(const float* __restrict__ w, const float* __restrict__ wb)
{
    int m = blockIdx.x;
    long long base = (long long)m * PD;
    float p = 0.0f;
    for (int d = threadIdx.x; d < PD; d += 256) {
        p = fmaf(g_h[base + d],   w[d],          p);
        p = fmaf(g_ctx[base + d], w[PD + d],     p);
        p = fmaf(g_x[base + d],   w[2 * PD + d], p);
    }
    p = blockSum(p);
    if (threadIdx.x == 0)
        g_pgen[m] = 1.0f / (1.0f + expf(-(p + wb[0])));
}

// online softmax over V, scaled by p_gen, fused with copy-scatter
__global__ void softmax_v2(float* __restrict__ out, const int* __restrict__ story)
{
    int o = blockIdx.x;
    long long base = (long long)o * PV;
    int s = o >> 6, b = (o >> 3) & 7, l = o & 7;
    int m = s * 64 + l * 8 + b;
    const float4* src = reinterpret_cast<const float4*>(out + base);
    float mx = -INFINITY, sm = 0.0f;
    for (int i = threadIdx.x; i < PV / 4; i += 256) {
        float4 v = src[i];
        float lm = fmaxf(fmaxf(v.x, v.y), fmaxf(v.z, v.w));
        if (lm > mx) { sm *= expf(mx - lm); mx = lm; }
        sm += expf(v.x - mx) + expf(v.y - mx) + expf(v.z - mx) + expf(v.w - mx);
    }
    __shared__ float smx[256], ssm[256];
    smx[threadIdx.x] = mx; ssm[threadIdx.x] = sm;
    __syncthreads();
    for (int st = 128; st; st >>= 1) {
        if (threadIdx.x < st) {
            float m1 = smx[threadIdx.x], s1 = ssm[threadIdx.x];
            float m2 = smx[threadIdx.x + st], s2 = ssm[threadIdx.x + st];
            float nm = fmaxf(m1, m2);
            smx[threadIdx.x] = nm;
            ssm[threadIdx.x] = s1 * expf(m1 - nm) + s2 * expf(m2 - nm);
        }
        __syncthreads();
    }
    float M = smx[0];
    float pg = g_pgen[m];
    float sc = pg / ssm[0];
    float4* dst = reinterpret_cast<float4*>(out + base);
    for (int i = threadIdx.x; i < PV / 4; i += 256) {
        float4 v = dst[i];
        v.x = expf(v.x - M) * sc; v.y = expf(v.y - M) * sc;
        v.z = expf(v.z - M) * sc; v.w = expf(v.w - M) * sc;
        dst[i] = v;
    }
    __syncthreads();
    float w = 1.0f - pg;
    for (int t = threadIdx.x; t < PT; t += 256) {
        int tok = story[b * PT + t];
        atomicAdd(&out[base + tok], w * g_probs[(long long)m * PT + t]);
    }
}

__global__ void gate_kernel(float* __restrict__ out, const float* __restrict__ wg,
                            const float* __restrict__ bg)
{
    int o = blockIdx.x;
    int s = o / (PB * PG);
    int b = (o % (PB * PG)) / PG;
    int g = o % PG;
    int m = s * 64 + b;
    float p = 0.0f;
    for (int d = threadIdx.x; d < PD; d += 128)
        p = fmaf(g_ctx[(long long)m * PD + d], wg[g * PD + d], p);
    p = blockSum(p);
    if (threadIdx.x == 0) out[OUT_PTR_ELEMS + o] = p + bg[g];
}

// ---------------- launch ----------------
extern "C" void kernel_launch(void* const* d_in, const int* in_sizes, int n_in,
                              void* d_out, int out_size)
{
    const float* enc_h   = (const float*)d_in[0];
    const float* enc_out = (const float*)d_in[1];
    const int*   story   = (const int*)d_in[2];
    const int*   trg     = (const int*)d_in[3];
    const float* emb     = (const float*)d_in[4];
    const float* w_ih    = (const float*)d_in[5];
    const float* w_hh    = (const float*)d_in[6];
    const float* b_ih    = (const float*)d_in[7];
    const float* b_hh    = (const float*)d_in[8];
    const float* w_rw    = (const float*)d_in[9];
    const float* w_rb    = (const float*)d_in[10];
    const float* w_gw    = (const float*)d_in[11];
    const float* w_gb    = (const float*)d_in[12];
    const float* slot    = (const float*)d_in[13];
    float* out = (float*)d_out;

    float *pgi, *psc, *pcx;
    __nv_bfloat16 *pB2, *pA2h, *pA2x, *pW2, *pE2, *pET2, *pS2;
    cudaGetSymbolAddress((void**)&pgi,  g_gi);
    cudaGetSymbolAddress((void**)&psc,  g_scores);
    cudaGetSymbolAddress((void**)&pcx,  g_ctx);
    cudaGetSymbolAddress((void**)&pB2,  g_B2);
    cudaGetSymbolAddress((void**)&pA2h, g_A2h);
    cudaGetSymbolAddress((void**)&pA2x, g_A2x);
    cudaGetSymbolAddress((void**)&pW2,  g_W2);
    cudaGetSymbolAddress((void**)&pE2,  g_E2);
    cudaGetSymbolAddress((void**)&pET2, g_ET2);
    cudaGetSymbolAddress((void**)&pS2,  g_S2);

    cudaFuncSetAttribute(mma_gemm<false>, cudaFuncAttributeMaxDynamicSharedMemorySize, MMA_SMEM);
    cudaFuncSetAttribute(mma_gemm<true>,  cudaFuncAttributeMaxDynamicSharedMemorySize, MMA_SMEM);

    // 1) inputs + operand splits
    build_x<<<(SLB * PD) / 256, 256>>>(emb, slot, trg);
    split_generic<<<PV, 256>>>(emb, pB2, 8, (long long)PV * 256);          // embedding
    split_generic<<<D3, 256>>>(w_ih, pW2, 8, (long long)D3 * 256);         // w_ih
    split_generic<<<PB * PT, 256>>>(enc_out, pE2, 8, (long long)PB * PT * 256);  // enc k-major
    trans_split<<<dim3(PT / 32, PD / 32, PB), dim3(32, 8)>>>(enc_out, pET2);     // enc^T

    // 2) gh = h0 @ w_hh^T + b_hh
    gh_kernel<<<(PB * D3 + 255) / 256, 256>>>(enc_h, w_hh, b_hh);

    // 3) gi = x @ w_ih^T   (M=1024, N=3072, K=1024)
    mma_gemm<false><<<dim3(8, 24, 1), 256, MMA_SMEM>>>(
        pA2x, 2048, 0, pW2, 2048, 0, pgi, D3, 0, 1024);

    // 4) GRU combine -> h (+ split)
    gru_kernel<<<(SLB * PD) / 256, 256>>>(b_ih, enc_h);

    // 5) scores = h . enc  (per-b: M=128, N=512, K=1024)
    mma_gemm<false><<<dim3(1, 4, 8), 256, MMA_SMEM>>>(
        pA2h, 8 * 2048, 2048, pE2, 2048, (long long)PT * 2048,
        psc, 8 * 512, 512, 1024);

    // 6) probs = softmax_t(scores)
    probs_kernel<<<SLB, 256>>>();

    // 7) split scores; context = scores @ enc  (per-b: M=128, N=1024, K=512)
    split_generic<<<SLB / 2, 256>>>(psc, pS2, 7, (long long)SLB * 128);
    mma_gemm<false><<<dim3(1, 8, 8), 256, MMA_SMEM>>>(
        pS2, 8 * 1024, 1024, pET2, 1024, (long long)PD * 1024,
        pcx, 8 * 1024, 1024, 512);

    // 8) p_gen
    pgen_kernel<<<SLB, 256>>>(w_rw, w_rb);

    // 9) logits = h @ E^T, permuted into out (M=1024, N=32000, K=1024)
    mma_gemm<true><<<dim3(8, 250, 1), 256, MMA_SMEM>>>(
        pA2h, 2048, 0, pB2, 2048, 0, out, 0, 0, 1024);

    // 10) softmax over V * p_gen + fused copy scatter
    softmax_v2<<<SLB, 256>>>(out, story);

    // 11) gate outputs
    gate_kernel<<<PS * PB * PG, 128>>>(out, w_gw, w_gb);
}

// round 6
// speedup vs baseline: 3.0559x; 1.0467x over previous
#include <cuda_runtime.h>
#include <cuda_bf16.h>
#include <math.h>
#include <stdint.h>

// Problem constants
#define PS   16
#define PB   8
#define PL   8
#define PV   32000
#define PD   1024
#define PT   512
#define PG   3
#define SLB  1024
#define D3   3072
#define NTILES 250            // PV / 128
#define OUT_PTR_ELEMS 32768000LL

// ---------------- device scratch ----------------
__device__ float g_x[SLB * PD];
__device__ float g_h[SLB * PD];
__device__ float g_gi[SLB * D3];
__device__ float g_gh[PB * D3];
__device__ float g_scores[SLB * PT];
__device__ float g_probs[SLB * PT];
__device__ float g_ctx[SLB * PD];
__device__ float g_pgen[SLB];
__device__ float2 g_part2[SLB * NTILES];   // per (out-row, n-tile) (max, sumexp)
__device__ float2 g_rowMS[SLB];            // per out-row (M, pgen/S)
// split bf16 operands, pitch 2K: [0,K)=hi, [K,2K)=lo
__device__ __nv_bfloat16 g_B2[(long long)PV * 2048];
__device__ __nv_bfloat16 g_A2h[SLB * 2048];
__device__ __nv_bfloat16 g_A2x[SLB * 2048];
__device__ __nv_bfloat16 g_W2[D3 * 2048];
__device__ __nv_bfloat16 g_E2[(long long)PB * PT * 2048];
__device__ __nv_bfloat16 g_ET2[(long long)PB * PD * 1024];
__device__ __nv_bfloat16 g_S2[SLB * 1024];

// ---------------- helpers ----------------
__device__ __forceinline__ uint32_t smem_u32(const void* p) {
    uint32_t a;
    asm("{ .reg .u64 t; cvta.to.shared.u64 t, %1; cvt.u32.u64 %0, t; }" : "=r"(a) : "l"(p));
    return a;
}
__device__ __forceinline__ void cp16(uint32_t s, const void* g) {
    asm volatile("cp.async.cg.shared.global [%0], [%1], 16;" :: "r"(s), "l"(g) : "memory");
}
__device__ __forceinline__ void cp_commit() {
    asm volatile("cp.async.commit_group;" ::: "memory");
}
template <int N>
__device__ __forceinline__ void cp_wait() {
    asm volatile("cp.async.wait_group %0;" :: "n"(N) : "memory");
}
__device__ __forceinline__ void mma16816(float& c0, float& c1, float& c2, float& c3,
                                         uint32_t a0, uint32_t a1, uint32_t a2, uint32_t a3,
                                         uint32_t b0, uint32_t b1) {
    asm volatile("mma.sync.aligned.m16n8k16.row.col.f32.bf16.bf16.f32 "
                 "{%0,%1,%2,%3}, {%4,%5,%6,%7}, {%8,%9}, {%0,%1,%2,%3};"
                 : "+f"(c0), "+f"(c1), "+f"(c2), "+f"(c3)
                 : "r"(a0), "r"(a1), "r"(a2), "r"(a3), "r"(b0), "r"(b1));
}
__device__ __forceinline__ void ldsm4(uint32_t& r0, uint32_t& r1, uint32_t& r2, uint32_t& r3,
                                      uint32_t addr) {
    asm volatile("ldmatrix.sync.aligned.m8n8.x4.shared.b16 {%0,%1,%2,%3}, [%4];"
                 : "=r"(r0), "=r"(r1), "=r"(r2), "=r"(r3) : "r"(addr));
}
__device__ __forceinline__ void split2(float v, __nv_bfloat16& hi, __nv_bfloat16& lo) {
    hi = __float2bfloat16(v);
    lo = __float2bfloat16(v - __bfloat162float(hi));
}

// ---------------- reductions ----------------
__device__ __forceinline__ float warpMax(float v) {
    #pragma unroll
    for (int o = 16; o; o >>= 1) v = fmaxf(v, __shfl_xor_sync(0xffffffffu, v, o));
    return v;
}
__device__ __forceinline__ float warpSum(float v) {
    #pragma unroll
    for (int o = 16; o; o >>= 1) v += __shfl_xor_sync(0xffffffffu, v, o);
    return v;
}
__device__ float blockSum(float v) {
    __shared__ float sm[32];
    v = warpSum(v);
    int w = threadIdx.x >> 5, l = threadIdx.x & 31;
    __syncthreads();
    if (l == 0) sm[w] = v;
    __syncthreads();
    int nw = (blockDim.x + 31) >> 5;
    v = (threadIdx.x < nw) ? sm[threadIdx.x] : 0.0f;
    if (w == 0) v = warpSum(v);
    if (threadIdx.x == 0) sm[0] = v;
    __syncthreads();
    return sm[0];
}
__device__ float blockMax(float v) {
    __shared__ float sm[32];
    v = warpMax(v);
    int w = threadIdx.x >> 5, l = threadIdx.x & 31;
    __syncthreads();
    if (l == 0) sm[w] = v;
    __syncthreads();
    int nw = (blockDim.x + 31) >> 5;
    v = (threadIdx.x < nw) ? sm[threadIdx.x] : -INFINITY;
    if (w == 0) v = warpMax(v);
    if (threadIdx.x == 0) sm[0] = v;
    __syncthreads();
    return sm[0];
}

// ---------------- split kernels ----------------
__global__ void split_generic(const float* __restrict__ src, __nv_bfloat16* __restrict__ dst,
                              int k4shift, long long total4)
{
    long long idx = (long long)blockIdx.x * 256 + threadIdx.x;
    if (idx >= total4) return;
    long long row = idx >> k4shift;
    int c4 = (int)(idx & ((1 << k4shift) - 1));
    int K = 4 << k4shift;
    float4 v = reinterpret_cast<const float4*>(src)[idx];
    __nv_bfloat162 h0 = __floats2bfloat162_rn(v.x, v.y);
    __nv_bfloat162 h1 = __floats2bfloat162_rn(v.z, v.w);
    float2 f0 = __bfloat1622float2(h0);
    float2 f1 = __bfloat1622float2(h1);
    __nv_bfloat162 l0 = __floats2bfloat162_rn(v.x - f0.x, v.y - f0.y);
    __nv_bfloat162 l1 = __floats2bfloat162_rn(v.z - f1.x, v.w - f1.y);
    long long base = row * (2LL * K);
    __nv_bfloat162* dh = reinterpret_cast<__nv_bfloat162*>(dst + base + c4 * 4);
    dh[0] = h0; dh[1] = h1;
    __nv_bfloat162* dl = reinterpret_cast<__nv_bfloat162*>(dst + base + K + c4 * 4);
    dl[0] = l0; dl[1] = l1;
}

__global__ void trans_split(const float* __restrict__ enc, __nv_bfloat16* __restrict__ dst)
{
    __shared__ float tile[32][33];
    int b = blockIdx.z;
    int d0 = blockIdx.y * 32;
    int t0 = blockIdx.x * 32;
    int tx = threadIdx.x, ty = threadIdx.y;
    const float* src = enc + ((long long)b * PT + t0) * PD + d0;
    #pragma unroll
    for (int j = 0; j < 4; j++)
        tile[ty + j * 8][tx] = src[(ty + j * 8) * PD + tx];
    __syncthreads();
    #pragma unroll
    for (int j = 0; j < 4; j++) {
        int d = d0 + ty + j * 8;
        float v = tile[tx][ty + j * 8];
        __nv_bfloat16 hi, lo; split2(v, hi, lo);
        long long ro = ((long long)(b << 10) + d) * 1024 + t0 + tx;
        dst[ro] = hi;
        dst[ro + 512] = lo;
    }
}

// ---------------- unified HMMA split-precision GEMM ----------------
// CTA tile 128x128, 256 thr (8 warps 2m x 4n, warp 64x32), k-chunk 32,
// 3-stage cp.async, 32KB/stage -> 2 CTAs/SM, ldmatrix fragment loads.
// PERMUTE: logits variant -> permuted C rows + per-tile softmax partials.
#define STAGE_B 32768
#define MMA_SMEM (3 * STAGE_B)

template <bool PERMUTE>
__global__ void __launch_bounds__(256, 2) mma_gemm(
    const __nv_bfloat16* __restrict__ A2, long long a_rs, long long a_batch,
    const __nv_bfloat16* __restrict__ B2, long long b_rs, long long b_batch,
    float* __restrict__ C, long long c_rs, long long c_batch,
    int K)
{
    extern __shared__ char smd[];
    const uint32_t sbase = smem_u32(smd);
    const int tid = threadIdx.x;
    const int wid = tid >> 5;
    const int lane = tid & 31;
    const int lr = lane >> 2;
    const int mr = (wid & 1) * 64;
    const int nc = (wid >> 1) * 32;
    const long long m0 = (long long)blockIdx.x * 128;
    const long long n0 = (long long)blockIdx.y * 128;
    const int z = blockIdx.z;
    const __nv_bfloat16* Ab = A2 + (long long)z * a_batch;
    const __nv_bfloat16* Bb = B2 + (long long)z * b_batch;
    const int CH = K >> 5;

    // ldmatrix per-lane base offsets (row*64 XOR swizzle XOR col-half)
    const int g3 = lane >> 3;      // 0..3
    const int i8 = lane & 7;
    uint32_t PA[4], PBo[2];
    #pragma unroll
    for (int fm = 0; fm < 4; fm++) {
        uint32_t r = (uint32_t)(mr + fm * 16 + (g3 & 1) * 8 + i8);
        PA[fm] = (r * 64) ^ (((r >> 1) & 3) << 4) ^ ((uint32_t)(g3 >> 1) << 4);
    }
    #pragma unroll
    for (int fn2 = 0; fn2 < 2; fn2++) {
        uint32_t r = (uint32_t)(nc + fn2 * 16 + (g3 >> 1) * 8 + i8);
        PBo[fn2] = (r * 64) ^ (((r >> 1) & 3) << 4) ^ ((uint32_t)(g3 & 1) << 4);
    }

    float acc[4][4][4];
    #pragma unroll
    for (int i = 0; i < 4; i++)
        #pragma unroll
        for (int j = 0; j < 4; j++)
            #pragma unroll
            for (int k = 0; k < 4; k++) acc[i][j][k] = 0.0f;

    auto issue = [&](int c) {
        const int koff = c << 5;
        const uint32_t st = sbase + (uint32_t)((c % 3) * STAGE_B);
        #pragma unroll
        for (int i = 0; i < 2; i++) {
            const int idx = tid + i * 256;
            const int r = idx >> 2, g = idx & 3;
            const uint32_t so = (uint32_t)(r * 64 + ((g ^ ((r >> 1) & 3)) << 4));
            const __nv_bfloat16* a = Ab + (m0 + r) * a_rs + koff + g * 8;
            cp16(st + so, a);
            cp16(st + 8192 + so, a + K);
            const __nv_bfloat16* b = Bb + (n0 + r) * b_rs + koff + g * 8;
            cp16(st + 16384 + so, b);
            cp16(st + 24576 + so, b + K);
        }
        cp_commit();
    };

    issue(0); issue(1);

    #pragma unroll 1
    for (int c = 0; c < CH; c++) {
        cp_wait<1>();
        __syncthreads();
        if (c + 2 < CH) issue(c + 2);

        const uint32_t st = sbase + (uint32_t)((c % 3) * STAGE_B);

        #pragma unroll
        for (int kc2 = 0; kc2 < 2; kc2++) {
            const uint32_t kx = (uint32_t)kc2 << 5;
            uint32_t ah[4][4], al[4][4], bh[4][2], bl[4][2];
            #pragma unroll
            for (int fm = 0; fm < 4; fm++)
                ldsm4(ah[fm][0], ah[fm][1], ah[fm][2], ah[fm][3], st + (PA[fm] ^ kx));
            #pragma unroll
            for (int fm = 0; fm < 4; fm++)
                ldsm4(al[fm][0], al[fm][1], al[fm][2], al[fm][3], st + 8192 + (PA[fm] ^ kx));
            #pragma unroll
            for (int fn2 = 0; fn2 < 2; fn2++)
                ldsm4(bh[fn2 * 2][0], bh[fn2 * 2][1], bh[fn2 * 2 + 1][0], bh[fn2 * 2 + 1][1],
                      st + 16384 + (PBo[fn2] ^ kx));
            #pragma unroll
            for (int fn2 = 0; fn2 < 2; fn2++)
                ldsm4(bl[fn2 * 2][0], bl[fn2 * 2][1], bl[fn2 * 2 + 1][0], bl[fn2 * 2 + 1][1],
                      st + 24576 + (PBo[fn2] ^ kx));

            #pragma unroll
            for (int fm = 0; fm < 4; fm++)
                #pragma unroll
                for (int fn = 0; fn < 4; fn++) {
                    mma16816(acc[fm][fn][0], acc[fm][fn][1], acc[fm][fn][2], acc[fm][fn][3],
                             ah[fm][0], ah[fm][1], ah[fm][2], ah[fm][3], bh[fn][0], bh[fn][1]);
                    mma16816(acc[fm][fn][0], acc[fm][fn][1], acc[fm][fn][2], acc[fm][fn][3],
                             ah[fm][0], ah[fm][1], ah[fm][2], ah[fm][3], bl[fn][0], bl[fn][1]);
                    mma16816(acc[fm][fn][0], acc[fm][fn][1], acc[fm][fn][2], acc[fm][fn][3],
                             al[fm][0], al[fm][1], al[fm][2], al[fm][3], bh[fn][0], bh[fn][1]);
                }
        }
    }

    // store C
    #pragma unroll
    for (int fm = 0; fm < 4; fm++) {
        const int mrow0 = (int)m0 + mr + fm * 16 + lr;
        const int mrow1 = mrow0 + 8;
        long long ro0, ro1;
        if (PERMUTE) {
            int s0 = mrow0 >> 6, l0 = (mrow0 >> 3) & 7, b0 = mrow0 & 7;
            int s1 = mrow1 >> 6, l1 = (mrow1 >> 3) & 7, b1 = mrow1 & 7;
            ro0 = (long long)((s0 * 8 + b0) * 8 + l0) * (long long)PV;
            ro1 = (long long)((s1 * 8 + b1) * 8 + l1) * (long long)PV;
        } else {
            ro0 = (long long)z * c_batch + (long long)mrow0 * c_rs;
            ro1 = (long long)z * c_batch + (long long)mrow1 * c_rs;
        }
        #pragma unroll
        for (int fn = 0; fn < 4; fn++) {
            const long long col = n0 + nc + fn * 8 + (lane & 3) * 2;
            *reinterpret_cast<float2*>(C + ro0 + col) = make_float2(acc[fm][fn][0], acc[fm][fn][1]);
            *reinterpret_cast<float2*>(C + ro1 + col) = make_float2(acc[fm][fn][2], acc[fm][fn][3]);
        }
    }

    // softmax partials (logits only): per CTA-row (max, sumexp) over 128 cols
    if (PERMUTE) {
        cp_wait<0>();
        __syncthreads();
        float2* part = reinterpret_cast<float2*>(smd);   // [128][4]
        #pragma unroll
        for (int fm = 0; fm < 4; fm++) {
            #pragma unroll
            for (int half = 0; half < 2; half++) {
                float mx = -1e30f;
                #pragma unroll
                for (int fn = 0; fn < 4; fn++) {
                    mx = fmaxf(mx, fmaxf(acc[fm][fn][half * 2], acc[fm][fn][half * 2 + 1]));
                }
                float se = 0.0f;
                #pragma unroll
                for (int fn = 0; fn < 4; fn++) {
                    se += __expf(acc[fm][fn][half * 2] - mx)
                        + __expf(acc[fm][fn][half * 2 + 1] - mx);
                }
                #pragma unroll
                for (int off = 1; off <= 2; off <<= 1) {
                    float mo = __shfl_xor_sync(0xffffffffu, mx, off);
                    float so = __shfl_xor_sync(0xffffffffu, se, off);
                    float nm = fmaxf(mx, mo);
                    se = se * __expf(mx - nm) + so * __expf(mo - nm);
                    mx = nm;
                }
                if ((lane & 3) == 0) {
                    int rloc = mr + fm * 16 + lr + half * 8;
                    part[rloc * 4 + (wid >> 1)] = make_float2(mx, se);
                }
            }
        }
        __syncthreads();
        if (tid < 128) {
            float2 p0 = part[tid * 4 + 0];
            float2 p1 = part[tid * 4 + 1];
            float2 p2 = part[tid * 4 + 2];
            float2 p3 = part[tid * 4 + 3];
            float M = fmaxf(fmaxf(p0.x, p1.x), fmaxf(p2.x, p3.x));
            float S = p0.y * __expf(p0.x - M) + p1.y * __expf(p1.x - M)
                    + p2.y * __expf(p2.x - M) + p3.y * __expf(p3.x - M);
            int mrow = (int)m0 + tid;
            int s = mrow >> 6, l = (mrow >> 3) & 7, b = mrow & 7;
            int o = (s * 8 + b) * 8 + l;
            g_part2[o * NTILES + blockIdx.y] = make_float2(M, S);
        }
    }
}

// ---------------- small kernels ----------------
__global__ void gh_kernel(const float* __restrict__ h0, const float* __restrict__ whh,
                          const float* __restrict__ bhh)
{
    int i = blockIdx.x * 256 + threadIdx.x;
    if (i >= PB * D3) return;
    int b = i / D3, e = i % D3;
    float acc = bhh[e];
    const float4* hr = reinterpret_cast<const float4*>(h0 + b * PD);
    const float4* wr = reinterpret_cast<const float4*>(whh + (long long)e * PD);
    #pragma unroll 4
    for (int k = 0; k < PD / 4; k++) {
        float4 a = hr[k], w = wr[k];
        acc = fmaf(a.x, w.x, acc); acc = fmaf(a.y, w.y, acc);
        acc = fmaf(a.z, w.z, acc); acc = fmaf(a.w, w.w, acc);
    }
    g_gh[i] = acc;
}

__global__ void build_x(const float* __restrict__ emb, const float* __restrict__ slot,
                        const int* __restrict__ trg)
{
    int idx = blockIdx.x * 256 + threadIdx.x;
    int d = idx & (PD - 1);
    int m = idx >> 10;
    int s = m >> 6, l = (m >> 3) & 7, b = m & 7;
    float v;
    if (l == 0) v = slot[s * PD + d];
    else {
        int tok = trg[b * (PS * PL) + s * PL + (l - 1)];
        v = emb[(long long)tok * PD + d];
    }
    g_x[idx] = v;
    __nv_bfloat16 hi, lo; split2(v, hi, lo);
    g_A2x[m * 2048 + d] = hi;
    g_A2x[m * 2048 + 1024 + d] = lo;
}

__global__ void gru_kernel(const float* __restrict__ bih, const float* __restrict__ h0)
{
    int idx = blockIdx.x * 256 + threadIdx.x;
    int d = idx & (PD - 1);
    int m = idx >> 10;
    int b = m & 7;
    long long gb = (long long)m * D3;
    float ir = g_gi[gb + d]          + bih[d];
    float iz = g_gi[gb + PD + d]     + bih[PD + d];
    float in = g_gi[gb + 2 * PD + d] + bih[2 * PD + d];
    float hr = g_gh[b * D3 + d];
    float hz = g_gh[b * D3 + PD + d];
    float hn = g_gh[b * D3 + 2 * PD + d];
    float r = 1.0f / (1.0f + expf(-(ir + hr)));
    float z = 1.0f / (1.0f + expf(-(iz + hz)));
    float n = tanhf(in + r * hn);
    float h = (1.0f - z) * n + z * h0[b * PD + d];
    g_h[idx] = h;
    __nv_bfloat16 hi, lo; split2(h, hi, lo);
    g_A2h[m * 2048 + d] = hi;
    g_A2h[m * 2048 + 1024 + d] = lo;
}

// probs = softmax_t(scores) + fused split of raw scores into S2
__global__ void probs_kernel()
{
    int m = blockIdx.x;
    long long base = (long long)m * PT;
    int t = threadIdx.x;
    float v0 = g_scores[base + t];
    float v1 = g_scores[base + t + 256];
    float mx = blockMax(fmaxf(v0, v1));
    float e0 = __expf(v0 - mx), e1 = __expf(v1 - mx);
    float sum = blockSum(e0 + e1);
    float inv = 1.0f / sum;
    g_probs[base + t] = e0 * inv;
    g_probs[base + t + 256] = e1 * inv;
    __nv_bfloat16 h, lo;
    split2(v0, h, lo);
    g_S2[m * 1024 + t] = h; g_S2[m * 1024 + 512 + t] = lo;
    split2(v1, h, lo);
    g_S2[m * 1024 + t + 256] = h; g_S2[m * 1024 + 512 + t + 256] = lo;
}

__global__ void pgen_kernel(const float* __restrict__ w, const float* __restrict__ wb)
{
    int m = blockIdx.x;
    long long base = (long long)m * PD;
    float p = 0.0f;
    for (int d = threadIdx.x; d < PD; d += 256) {
        p = fmaf(g_h[base + d],   w[d],          p);
        p = fmaf(g_ctx[base + d], w[PD + d],     p);
        p = fmaf(g_x[base + d],   w[2 * PD + d], p);
    }
    p = blockSum(p);
    if (threadIdx.x == 0)
        g_pgen[m] = 1.0f / (1.0f + expf(-(p + wb[0])));
}

// combine per-tile (max,sumexp) partials -> per-row (M, pg/S)
__global__ void combine_kernel()
{
    int o = blockIdx.x;
    int i = threadIdx.x;
    float M = -1e30f, S = 0.0f;
    if (i < NTILES) {
        float2 p = g_part2[o * NTILES + i];
        M = p.x; S = p.y;
    }
    __shared__ float smx[256], ssm[256];
    smx[i] = M; ssm[i] = S;
    __syncthreads();
    for (int st = 128; st; st >>= 1) {
        if (i < st) {
            float m1 = smx[i], s1 = ssm[i];
            float m2 = smx[i + st], s2 = ssm[i + st];
            float nm = fmaxf(m1, m2);
            smx[i] = nm;
            ssm[i] = s1 * __expf(m1 - nm) + s2 * __expf(m2 - nm);
        }
        __syncthreads();
    }
    if (i == 0) {
        int s = o >> 6, b = (o >> 3) & 7, l = o & 7;
        int m = s * 64 + l * 8 + b;
        float pg = g_pgen[m];
        g_rowMS[o] = make_float2(smx[0], pg / ssm[0]);
    }
}

// final: out = exp(x - M) * pg/S, then scatter (1-pg)*probs
__global__ void final_kernel(float* __restrict__ out, const int* __restrict__ story)
{
    int o = blockIdx.x;
    float2 ms = g_rowMS[o];
    long long base = (long long)o * PV;
    int s = o >> 6, b = (o >> 3) & 7, l = o & 7;
    int m = s * 64 + l * 8 + b;
    float4* dst = reinterpret_cast<float4*>(out + base);
    for (int i = threadIdx.x; i < PV / 4; i += 256) {
        float4 v = dst[i];
        v.x = __expf(v.x - ms.x) * ms.y;
        v.y = __expf(v.y - ms.x) * ms.y;
        v.z = __expf(v.z - ms.x) * ms.y;
        v.w = __expf(v.w - ms.x) * ms.y;
        dst[i] = v;
    }
    __syncthreads();
    float w = 1.0f - g_pgen[m];
    for (int t = threadIdx.x; t < PT; t += 256) {
        int tok = story[b * PT + t];
        atomicAdd(&out[base + tok], w * g_probs[(long long)m * PT + t]);
    }
}

__global__ void gate_kernel(float* __restrict__ out, const float* __restrict__ wg,
                            const float* __restrict__ bg)
{
    int o = blockIdx.x;
    int s = o / (PB * PG);
    int b = (o % (PB * PG)) / PG;
    int g = o % PG;
    int m = s * 64 + b;
    float p = 0.0f;
    for (int d = threadIdx.x; d < PD; d += 128)
        p = fmaf(g_ctx[(long long)m * PD + d], wg[g * PD + d], p);
    p = blockSum(p);
    if (threadIdx.x == 0) out[OUT_PTR_ELEMS + o] = p + bg[g];
}

// ---------------- launch ----------------
extern "C" void kernel_launch(void* const* d_in, const int* in_sizes, int n_in,
                              void* d_out, int out_size)
{
    const float* enc_h   = (const float*)d_in[0];
    const float* enc_out = (const float*)d_in[1];
    const int*   story   = (const int*)d_in[2];
    const int*   trg     = (const int*)d_in[3];
    const float* emb     = (const float*)d_in[4];
    const float* w_ih    = (const float*)d_in[5];
    const float* w_hh    = (const float*)d_in[6];
    const float* b_ih    = (const float*)d_in[7];
    const float* b_hh    = (const float*)d_in[8];
    const float* w_rw    = (const float*)d_in[9];
    const float* w_rb    = (const float*)d_in[10];
    const float* w_gw    = (const float*)d_in[11];
    const float* w_gb    = (const float*)d_in[12];
    const float* slot    = (const float*)d_in[13];
    float* out = (float*)d_out;

    float *pgi, *psc, *pcx;
    __nv_bfloat16 *pB2, *pA2h, *pA2x, *pW2, *pE2, *pET2, *pS2;
    cudaGetSymbolAddress((void**)&pgi,  g_gi);
    cudaGetSymbolAddress((void**)&psc,  g_scores);
    cudaGetSymbolAddress((void**)&pcx,  g_ctx);
    cudaGetSymbolAddress((void**)&pB2,  g_B2);
    cudaGetSymbolAddress((void**)&pA2h, g_A2h);
    cudaGetSymbolAddress((void**)&pA2x, g_A2x);
    cudaGetSymbolAddress((void**)&pW2,  g_W2);
    cudaGetSymbolAddress((void**)&pE2,  g_E2);
    cudaGetSymbolAddress((void**)&pET2, g_ET2);
    cudaGetSymbolAddress((void**)&pS2,  g_S2);

    cudaFuncSetAttribute(mma_gemm<false>, cudaFuncAttributeMaxDynamicSharedMemorySize, MMA_SMEM);
    cudaFuncSetAttribute(mma_gemm<true>,  cudaFuncAttributeMaxDynamicSharedMemorySize, MMA_SMEM);

    // 1-3) inputs + operand splits (order chosen so launch #4 = mma_gemm for ncu)
    build_x<<<(SLB * PD) / 256, 256>>>(emb, slot, trg);
    split_generic<<<D3, 256>>>(w_ih, pW2, 8, (long long)D3 * 256);
    split_generic<<<PV, 256>>>(emb, pB2, 8, (long long)PV * 256);

    // 4) gi = x @ w_ih^T   (M=1024, N=3072, K=1024)  <- profiled launch
    mma_gemm<false><<<dim3(8, 24, 1), 256, MMA_SMEM>>>(
        pA2x, 2048, 0, pW2, 2048, 0, pgi, D3, 0, 1024);

    // 5-7) enc splits + gh
    split_generic<<<PB * PT, 256>>>(enc_out, pE2, 8, (long long)PB * PT * 256);
    trans_split<<<dim3(PT / 32, PD / 32, PB), dim3(32, 8)>>>(enc_out, pET2);
    gh_kernel<<<(PB * D3 + 255) / 256, 256>>>(enc_h, w_hh, b_hh);

    // 8) GRU combine -> h (+ split)
    gru_kernel<<<(SLB * PD) / 256, 256>>>(b_ih, enc_h);

    // 9) scores = h . enc  (per-b: M=128, N=512, K=1024)
    mma_gemm<false><<<dim3(1, 4, 8), 256, MMA_SMEM>>>(
        pA2h, 8 * 2048, 2048, pE2, 2048, (long long)PT * 2048,
        psc, 8 * 512, 512, 1024);

    // 10) probs (+ S2 split)
    probs_kernel<<<SLB, 256>>>();

    // 11) context = scores @ enc  (per-b: M=128, N=1024, K=512)
    mma_gemm<false><<<dim3(1, 8, 8), 256, MMA_SMEM>>>(
        pS2, 8 * 1024, 1024, pET2, 1024, (long long)PD * 1024,
        pcx, 8 * 1024, 1024, 512);

    // 12) p_gen
    pgen_kernel<<<SLB, 256>>>(w_rw, w_rb);

    // 13) logits = h @ E^T, permuted into out + softmax partials
    mma_gemm<true><<<dim3(8, NTILES, 1), 256, MMA_SMEM>>>(
        pA2h, 2048, 0, pB2, 2048, 0, out, 0, 0, 1024);

    // 14) combine partials -> per-row (M, pg/S)
    combine_kernel<<<SLB, 256>>>();

    // 15) scale + scatter
    final_kernel<<<SLB, 256>>>(out, story);

    // 16) gate outputs
    gate_kernel<<<PS * PB * PG, 128>>>(out, w_gw, w_gb);
}